// round 2
// baseline (speedup 1.0000x reference)
#include <cuda_runtime.h>
#include <math.h>

#define BB 4
#define TT 2048
#define EE 1024
#define HH 64
#define MM (BB*TT)

// scratch for Q/K/V projections (device globals: allocation-free).
// Referenced ONLY from device code — host code must never take their address.
__device__ float g_q[MM*HH];
__device__ float g_k[MM*HH];
__device__ float g_v[MM*HH];

// ---------------------------------------------------------------------------
// Kernel 1: fused QKV projection.  C[M,64] = X[M,1024] * W[64,1024]^T + b
// grid = (M/64, 3), block = 256.  64x64 output tile, K-chunk 16, 4x4 per thread.
// ---------------------------------------------------------------------------
__global__ __launch_bounds__(256) void proj_kernel(
    const float* __restrict__ x,
    const float* __restrict__ Wq, const float* __restrict__ bq,
    const float* __restrict__ Wk, const float* __restrict__ bk,
    const float* __restrict__ Wv, const float* __restrict__ bv)
{
    __shared__ float As[64][17];
    __shared__ float Bs[64][17];

    const float* W;
    const float* bias;
    float* out;
    if (blockIdx.y == 0)      { W = Wq; bias = bq; out = g_q; }
    else if (blockIdx.y == 1) { W = Wk; bias = bk; out = g_k; }
    else                      { W = Wv; bias = bv; out = g_v; }

    const int row0 = blockIdx.x * 64;
    const int tid  = threadIdx.x;
    const int lr = tid >> 2;          // 0..63  : smem row to load
    const int lc = (tid & 3) << 2;    // 0,4,8,12 : col within 16-chunk
    const int ty = tid >> 4;          // 0..15
    const int tx = tid & 15;          // 0..15

    float acc[4][4];
#pragma unroll
    for (int i = 0; i < 4; i++)
#pragma unroll
        for (int j = 0; j < 4; j++) acc[i][j] = 0.0f;

    for (int kt = 0; kt < EE; kt += 16) {
        float4 a = *(const float4*)(x + (size_t)(row0 + lr) * EE + kt + lc);
        float4 w = *(const float4*)(W + (size_t)lr * EE + kt + lc);
        As[lr][lc+0] = a.x; As[lr][lc+1] = a.y; As[lr][lc+2] = a.z; As[lr][lc+3] = a.w;
        Bs[lr][lc+0] = w.x; Bs[lr][lc+1] = w.y; Bs[lr][lc+2] = w.z; Bs[lr][lc+3] = w.w;
        __syncthreads();
#pragma unroll
        for (int k = 0; k < 16; k++) {
            float av[4], bv2[4];
#pragma unroll
            for (int i = 0; i < 4; i++) av[i]  = As[ty*4+i][k];
#pragma unroll
            for (int j = 0; j < 4; j++) bv2[j] = Bs[tx*4+j][k];
#pragma unroll
            for (int i = 0; i < 4; i++)
#pragma unroll
                for (int j = 0; j < 4; j++) acc[i][j] += av[i] * bv2[j];
        }
        __syncthreads();
    }

#pragma unroll
    for (int i = 0; i < 4; i++) {
        size_t obase = (size_t)(row0 + ty*4 + i) * HH + tx*4;
#pragma unroll
        for (int j = 0; j < 4; j++)
            out[obase + j] = acc[i][j] + bias[tx*4 + j];
    }
}

// ---------------------------------------------------------------------------
// Kernel 2: causal flash attention.
// grid = (T/32, B), block = 256 (8 warps).  Each warp owns 4 query rows.
// KV tile = 64 keys.  Lane l handles keys (l, l+32) of each tile and output
// dims (l, l+32).  P values broadcast across the warp via shfl (no P smem).
// Reads g_q/g_k/g_v directly (device globals).
// ---------------------------------------------------------------------------
#define TQ 32
#define TK 64
#define LOG2E 1.4426950408889634f

__global__ __launch_bounds__(256) void attn_kernel(float* __restrict__ out)
{
    __shared__ float  Qs[TQ][HH];       // broadcast reads only -> no pad needed
    __shared__ float  Ks[TK][HH + 1];   // lane-per-key reads -> pad 65
    __shared__ float4 Vs4[TK][HH/4];    // row reads at lane offset -> no pad

    const int b   = blockIdx.y;
    const int qt0 = blockIdx.x * TQ;
    const int tid = threadIdx.x;
    const int w   = tid >> 5;
    const int l   = tid & 31;

    const float* qptr = g_q + ((size_t)b * TT + qt0) * HH;
    const float* kptr = g_k + (size_t)b * TT * HH;
    const float* vptr = g_v + (size_t)b * TT * HH;

    // load Q tile (2048 floats = 512 float4)
    {
        const float4* src = (const float4*)qptr;
        float4* dst = (float4*)&Qs[0][0];
        dst[tid]       = src[tid];
        dst[tid + 256] = src[tid + 256];
    }

    float m[4], lsum[4], o0[4], o1[4];
#pragma unroll
    for (int r = 0; r < 4; r++) { m[r] = -INFINITY; lsum[r] = 0.f; o0[r] = 0.f; o1[r] = 0.f; }

    const int ntiles = (qt0 + TQ - 1) / TK + 1;

    for (int kt = 0; kt < ntiles; kt++) {
        const int k0 = kt * TK;
        __syncthreads();   // previous tile's smem reads done (also covers Q load)
        // cooperative load of K and V tiles (each 64x64 fp32)
#pragma unroll
        for (int i = 0; i < 4; i++) {
            int idx = tid + i * 256;           // 0..1023
            int row = idx >> 4;                // 0..63
            int c4  = idx & 15;                // float4 index within row
            float4 kv = ((const float4*)(kptr + (size_t)(k0 + row) * HH))[c4];
            int cc = c4 << 2;
            Ks[row][cc+0] = kv.x; Ks[row][cc+1] = kv.y;
            Ks[row][cc+2] = kv.z; Ks[row][cc+3] = kv.w;
            Vs4[row][c4] = ((const float4*)(vptr + (size_t)(k0 + row) * HH))[c4];
        }
        __syncthreads();

        // ---- scores: s[r][0] = q_r . k_l ; s[r][1] = q_r . k_{l+32} ----
        float s0[4] = {0,0,0,0}, s1[4] = {0,0,0,0};
#pragma unroll 8
        for (int h = 0; h < HH; h++) {
            float ka = Ks[l][h];
            float kc = Ks[l + 32][h];
#pragma unroll
            for (int r = 0; r < 4; r++) {
                float qv = Qs[w*4 + r][h];
                s0[r] += qv * ka;
                s1[r] += qv * kc;
            }
        }

        // ---- online softmax update ----
        float p0[4], p1[4];
#pragma unroll
        for (int r = 0; r < 4; r++) {
            const int t = qt0 + w*4 + r;
            float u0 = (k0 + l      <= t) ? s0[r] * 0.125f : -INFINITY;
            float u1 = (k0 + l + 32 <= t) ? s1[r] * 0.125f : -INFINITY;
            float mx = fmaxf(u0, u1);
#pragma unroll
            for (int off = 16; off; off >>= 1)
                mx = fmaxf(mx, __shfl_xor_sync(0xffffffffu, mx, off));
            float mnew = fmaxf(m[r], mx);
            float f = exp2f((m[r] - mnew) * LOG2E);
            p0[r] = exp2f((u0 - mnew) * LOG2E);
            p1[r] = exp2f((u1 - mnew) * LOG2E);
            float ps = p0[r] + p1[r];
#pragma unroll
            for (int off = 16; off; off >>= 1)
                ps += __shfl_xor_sync(0xffffffffu, ps, off);
            lsum[r] = lsum[r] * f + ps;
            o0[r] *= f; o1[r] *= f;
            m[r] = mnew;
        }

        // ---- PV accumulate: o[r][h] += sum_s p[r][s] * V[s][h] ----
        const float* VsF = (const float*)Vs4;
#pragma unroll 8
        for (int sl = 0; sl < 32; sl++) {
            float v0 = VsF[sl * HH + l];
            float v1 = VsF[sl * HH + l + 32];
#pragma unroll
            for (int r = 0; r < 4; r++) {
                float pv = __shfl_sync(0xffffffffu, p0[r], sl);
                o0[r] += pv * v0;
                o1[r] += pv * v1;
            }
        }
#pragma unroll 8
        for (int sl = 0; sl < 32; sl++) {
            float v0 = VsF[(sl + 32) * HH + l];
            float v1 = VsF[(sl + 32) * HH + l + 32];
#pragma unroll
            for (int r = 0; r < 4; r++) {
                float pv = __shfl_sync(0xffffffffu, p1[r], sl);
                o0[r] += pv * v0;
                o1[r] += pv * v1;
            }
        }
    }

    // ---- epilogue ----
#pragma unroll
    for (int r = 0; r < 4; r++) {
        const int t = qt0 + w*4 + r;
        float inv = 1.0f / lsum[r];
        size_t obase = ((size_t)b * TT + t) * HH;
        out[obase + l]      = o0[r] * inv;
        out[obase + l + 32] = o1[r] * inv;
    }
}

// ---------------------------------------------------------------------------
extern "C" void kernel_launch(void* const* d_in, const int* in_sizes, int n_in,
                              void* d_out, int out_size)
{
    const float* x  = (const float*)d_in[0];
    const float* Wq = (const float*)d_in[1];
    const float* bq = (const float*)d_in[2];
    const float* Wk = (const float*)d_in[3];
    const float* bk = (const float*)d_in[4];
    const float* Wv = (const float*)d_in[5];
    const float* bv = (const float*)d_in[6];
    float* out = (float*)d_out;

    dim3 pgrid(MM / 64, 3);
    proj_kernel<<<pgrid, 256>>>(x, Wq, bq, Wk, bk, Wv, bv);

    dim3 agrid(TT / TQ, BB);
    attn_kernel<<<agrid, 256>>>(out);
}

// round 3
// speedup vs baseline: 1.5357x; 1.5357x over previous
#include <cuda_runtime.h>
#include <math.h>

#define BB 4
#define TT 2048
#define EE 1024
#define HH 64
#define MM (BB*TT)

// scratch for Q/K/V projections (device globals: allocation-free).
// Referenced ONLY from device code.
__device__ float g_q[MM*HH];
__device__ float g_k[MM*HH];
__device__ float g_v[MM*HH];

__device__ __forceinline__ unsigned f2tf32(float f) {
    unsigned u;
    asm("cvt.rna.tf32.f32 %0, %1;" : "=r"(u) : "f"(f));
    return u;
}

// ---------------------------------------------------------------------------
// Kernel 1: fused QKV projection via mma.sync tf32.
// C[M,64] = X[M,1024] * W[64,1024]^T + b
// grid = (M/64, 3), block = 128 (4 warps).  64x64 output tile, K-chunk 16.
// Warp w computes rows m0=w*16 .. m0+15, all 64 cols (8 n-frags of m16n8k8).
// ---------------------------------------------------------------------------
__global__ __launch_bounds__(128) void proj_mma_kernel(
    const float* __restrict__ x,
    const float* __restrict__ Wq, const float* __restrict__ bq,
    const float* __restrict__ Wk, const float* __restrict__ bk,
    const float* __restrict__ Wv, const float* __restrict__ bv)
{
    __shared__ unsigned As[64][20];   // X tile, tf32 bits, pad 20 (16B-aligned rows)
    __shared__ unsigned Ws[64][20];   // W tile, tf32 bits

    const float* W;
    const float* bias;
    float* out;
    if (blockIdx.y == 0)      { W = Wq; bias = bq; out = g_q; }
    else if (blockIdx.y == 1) { W = Wk; bias = bk; out = g_k; }
    else                      { W = Wv; bias = bv; out = g_v; }

    const int row0 = blockIdx.x * 64;
    const int tid  = threadIdx.x;
    const int wid  = tid >> 5;
    const int l    = tid & 31;
    const int g    = l >> 2;     // 0..7
    const int tg   = l & 3;      // 0..3
    const int m0   = wid * 16;

    // loader: 2 float4 of X and 2 float4 of W per thread per chunk.
    const int r_a = tid >> 2;          // rows 0..31
    const int r_b = r_a + 32;          // rows 32..63
    const int c_a = (tid & 3) * 4;     // col offset within 16-chunk

    float acc[8][4];
#pragma unroll
    for (int n = 0; n < 8; n++)
#pragma unroll
        for (int i = 0; i < 4; i++) acc[n][i] = 0.0f;

    // prefetch chunk 0
    float4 xa = *(const float4*)(x + (size_t)(row0 + r_a) * EE + c_a);
    float4 xb = *(const float4*)(x + (size_t)(row0 + r_b) * EE + c_a);
    float4 wa = *(const float4*)(W + (size_t)r_a * EE + c_a);
    float4 wb = *(const float4*)(W + (size_t)r_b * EE + c_a);

    for (int kc = 0; kc < EE; kc += 16) {
        // store prefetched chunk (converted to tf32)
        As[r_a][c_a+0] = f2tf32(xa.x); As[r_a][c_a+1] = f2tf32(xa.y);
        As[r_a][c_a+2] = f2tf32(xa.z); As[r_a][c_a+3] = f2tf32(xa.w);
        As[r_b][c_a+0] = f2tf32(xb.x); As[r_b][c_a+1] = f2tf32(xb.y);
        As[r_b][c_a+2] = f2tf32(xb.z); As[r_b][c_a+3] = f2tf32(xb.w);
        Ws[r_a][c_a+0] = f2tf32(wa.x); Ws[r_a][c_a+1] = f2tf32(wa.y);
        Ws[r_a][c_a+2] = f2tf32(wa.z); Ws[r_a][c_a+3] = f2tf32(wa.w);
        Ws[r_b][c_a+0] = f2tf32(wb.x); Ws[r_b][c_a+1] = f2tf32(wb.y);
        Ws[r_b][c_a+2] = f2tf32(wb.z); Ws[r_b][c_a+3] = f2tf32(wb.w);
        __syncthreads();

        if (kc + 16 < EE) {
            xa = *(const float4*)(x + (size_t)(row0 + r_a) * EE + kc + 16 + c_a);
            xb = *(const float4*)(x + (size_t)(row0 + r_b) * EE + kc + 16 + c_a);
            wa = *(const float4*)(W + (size_t)r_a * EE + kc + 16 + c_a);
            wb = *(const float4*)(W + (size_t)r_b * EE + kc + 16 + c_a);
        }

#pragma unroll
        for (int k8 = 0; k8 < 16; k8 += 8) {
            // A fragment (m16 x k8, row-major): a0=(g,tg) a1=(g+8,tg) a2=(g,tg+4) a3=(g+8,tg+4)
            unsigned a0 = As[m0 + g    ][tg     + k8];
            unsigned a1 = As[m0 + g + 8][tg     + k8];
            unsigned a2 = As[m0 + g    ][tg + 4 + k8];
            unsigned a3 = As[m0 + g + 8][tg + 4 + k8];
#pragma unroll
            for (int n0 = 0; n0 < 8; n0++) {
                // B fragment (k8 x n8, col-major): b0=B[tg][g]=W[n0*8+g][tg], b1=B[tg+4][g]
                unsigned b0 = Ws[n0 * 8 + g][tg     + k8];
                unsigned b1 = Ws[n0 * 8 + g][tg + 4 + k8];
                asm volatile(
                    "mma.sync.aligned.m16n8k8.row.col.f32.tf32.tf32.f32 "
                    "{%0,%1,%2,%3}, {%4,%5,%6,%7}, {%8,%9}, {%0,%1,%2,%3};"
                    : "+f"(acc[n0][0]), "+f"(acc[n0][1]), "+f"(acc[n0][2]), "+f"(acc[n0][3])
                    : "r"(a0), "r"(a1), "r"(a2), "r"(a3), "r"(b0), "r"(b1));
            }
        }
        __syncthreads();
    }

    // epilogue: C layout c0=(g,2tg) c1=(g,2tg+1) c2=(g+8,2tg) c3=(g+8,2tg+1)
#pragma unroll
    for (int n0 = 0; n0 < 8; n0++) {
        int col = n0 * 8 + 2 * tg;
        float b0 = bias[col], b1 = bias[col + 1];
        float2 v0 = make_float2(acc[n0][0] + b0, acc[n0][1] + b1);
        float2 v1 = make_float2(acc[n0][2] + b0, acc[n0][3] + b1);
        *(float2*)(out + (size_t)(row0 + m0 + g    ) * HH + col) = v0;
        *(float2*)(out + (size_t)(row0 + m0 + g + 8) * HH + col) = v1;
    }
}

// ---------------------------------------------------------------------------
// Kernel 2: causal flash attention (SIMT v3).
// grid = (T/32, B), block = 256 (8 warps), each warp owns 4 query rows.
// Heavy q-tiles launched first (reversed blockIdx).  KV tile = 64.
// float4 broadcasts for Q and P; P staged in smem (per-warp private rows).
// Dynamic smem: Qs[32][64] | Ks[64][65] | Vs[64][64] | Ps[32][64]
// ---------------------------------------------------------------------------
#define TQ 32
#define TK 64
#define LOG2E 1.4426950408889634f

#define SMEM_QS 0
#define SMEM_KS (TQ*HH)                     // 2048 floats
#define SMEM_VS (SMEM_KS + TK*(HH+1))       // +4160 = 6208
#define SMEM_PS (SMEM_VS + TK*HH)           // +4096 = 10304
#define SMEM_FLOATS (SMEM_PS + TQ*HH)       // +2048 = 12352 floats = 49408 B

__global__ __launch_bounds__(256) void attn_kernel(float* __restrict__ out)
{
    extern __shared__ float sm[];
    float* Qs = sm + SMEM_QS;   // [32][64]
    float* Ks = sm + SMEM_KS;   // [64][65]
    float* Vs = sm + SMEM_VS;   // [64][64]
    float* Ps = sm + SMEM_PS;   // [32][64]

    const int b   = blockIdx.y;
    const int qt0 = (gridDim.x - 1 - blockIdx.x) * TQ;   // heavy blocks first
    const int tid = threadIdx.x;
    const int w   = tid >> 5;
    const int l   = tid & 31;

    const float* qptr = g_q + ((size_t)b * TT + qt0) * HH;
    const float* kptr = g_k + (size_t)b * TT * HH;
    const float* vptr = g_v + (size_t)b * TT * HH;

    // load Q tile (2048 floats = 512 float4)
    {
        const float4* src = (const float4*)qptr;
        float4* dst = (float4*)Qs;
        dst[tid]       = src[tid];
        dst[tid + 256] = src[tid + 256];
    }

    float m[4], lsum[4], o0[4], o1[4];
#pragma unroll
    for (int r = 0; r < 4; r++) { m[r] = -INFINITY; lsum[r] = 0.f; o0[r] = 0.f; o1[r] = 0.f; }

    const int ntiles = (qt0 + TQ - 1) / TK + 1;

    for (int kt = 0; kt < ntiles; kt++) {
        const int k0 = kt * TK;
        __syncthreads();   // previous tile's smem reads done (also covers Q load)
        // cooperative load of K (scalar, padded 65) and V (float4) tiles
#pragma unroll
        for (int i = 0; i < 4; i++) {
            int idx = tid + i * 256;           // 0..1023
            int row = idx >> 4;                // 0..63
            int c4  = idx & 15;                // float4 index within row
            float4 kv = ((const float4*)(kptr + (size_t)(k0 + row) * HH))[c4];
            int cc = c4 << 2;
            float* kd = Ks + row * (HH + 1) + cc;
            kd[0] = kv.x; kd[1] = kv.y; kd[2] = kv.z; kd[3] = kv.w;
            ((float4*)(Vs + row * HH))[c4] = ((const float4*)(vptr + (size_t)(k0 + row) * HH))[c4];
        }
        __syncthreads();

        // ---- scores: s[r][0] = q_r . k_l ; s[r][1] = q_r . k_{l+32} ----
        float s0[4] = {0,0,0,0}, s1[4] = {0,0,0,0};
        const float* KrowA = Ks + l * (HH + 1);
        const float* KrowB = Ks + (l + 32) * (HH + 1);
#pragma unroll
        for (int hc = 0; hc < 16; hc++) {
            float qa[4][4];
#pragma unroll
            for (int r = 0; r < 4; r++)
                *(float4*)qa[r] = *(const float4*)(Qs + (w*4 + r) * HH + hc*4);
#pragma unroll
            for (int j = 0; j < 4; j++) {
                float ka = KrowA[hc*4 + j];
                float kc = KrowB[hc*4 + j];
#pragma unroll
                for (int r = 0; r < 4; r++) {
                    s0[r] += qa[r][j] * ka;
                    s1[r] += qa[r][j] * kc;
                }
            }
        }

        // ---- online softmax update ----
        float p0[4], p1[4];
#pragma unroll
        for (int r = 0; r < 4; r++) {
            const int t = qt0 + w*4 + r;
            float u0 = (k0 + l      <= t) ? s0[r] * 0.125f : -INFINITY;
            float u1 = (k0 + l + 32 <= t) ? s1[r] * 0.125f : -INFINITY;
            float mx = fmaxf(u0, u1);
#pragma unroll
            for (int off = 16; off; off >>= 1)
                mx = fmaxf(mx, __shfl_xor_sync(0xffffffffu, mx, off));
            float mnew = fmaxf(m[r], mx);
            float f = exp2f((m[r] - mnew) * LOG2E);
            p0[r] = exp2f((u0 - mnew) * LOG2E);
            p1[r] = exp2f((u1 - mnew) * LOG2E);
            float ps = p0[r] + p1[r];
#pragma unroll
            for (int off = 16; off; off >>= 1)
                ps += __shfl_xor_sync(0xffffffffu, ps, off);
            lsum[r] = lsum[r] * f + ps;
            o0[r] *= f; o1[r] *= f;
            m[r] = mnew;
        }

        // stage P to smem (per-warp private rows; warp-sync is enough)
#pragma unroll
        for (int r = 0; r < 4; r++) {
            Ps[(w*4 + r) * HH + l]      = p0[r];
            Ps[(w*4 + r) * HH + l + 32] = p1[r];
        }
        __syncwarp();

        // ---- PV accumulate: o[r][h] += sum_s p[r][s] * V[s][h] ----
#pragma unroll
        for (int slc = 0; slc < 16; slc++) {
            float pa[4][4];
#pragma unroll
            for (int r = 0; r < 4; r++)
                *(float4*)pa[r] = *(const float4*)(Ps + (w*4 + r) * HH + slc*4);
#pragma unroll
            for (int j = 0; j < 4; j++) {
                int sl = slc*4 + j;
                float v0 = Vs[sl * HH + l];
                float v1 = Vs[sl * HH + l + 32];
#pragma unroll
                for (int r = 0; r < 4; r++) {
                    o0[r] += pa[r][j] * v0;
                    o1[r] += pa[r][j] * v1;
                }
            }
        }
    }

    // ---- epilogue ----
#pragma unroll
    for (int r = 0; r < 4; r++) {
        const int t = qt0 + w*4 + r;
        float inv = 1.0f / lsum[r];
        size_t obase = ((size_t)b * TT + t) * HH;
        out[obase + l]      = o0[r] * inv;
        out[obase + l + 32] = o1[r] * inv;
    }
}

// ---------------------------------------------------------------------------
extern "C" void kernel_launch(void* const* d_in, const int* in_sizes, int n_in,
                              void* d_out, int out_size)
{
    const float* x  = (const float*)d_in[0];
    const float* Wq = (const float*)d_in[1];
    const float* bq = (const float*)d_in[2];
    const float* Wk = (const float*)d_in[3];
    const float* bk = (const float*)d_in[4];
    const float* Wv = (const float*)d_in[5];
    const float* bv = (const float*)d_in[6];
    float* out = (float*)d_out;

    dim3 pgrid(MM / 64, 3);
    proj_mma_kernel<<<pgrid, 128>>>(x, Wq, bq, Wk, bk, Wv, bv);

    const int smem_bytes = SMEM_FLOATS * sizeof(float);   // 49408
    cudaFuncSetAttribute(attn_kernel, cudaFuncAttributeMaxDynamicSharedMemorySize, smem_bytes);
    dim3 agrid(TT / TQ, BB);
    attn_kernel<<<agrid, 256, smem_bytes>>>(out);
}

// round 4
// speedup vs baseline: 2.4690x; 1.6078x over previous
#include <cuda_runtime.h>
#include <math.h>

#define BB 4
#define TT 2048
#define EE 1024
#define HH 64
#define MM (BB*TT)

// Q/K/V scratch (stored ALREADY tf32-rounded by proj epilogue)
__device__ float g_q[MM*HH];
__device__ float g_k[MM*HH];
__device__ float g_v[MM*HH];

__device__ __forceinline__ unsigned f2tf32(float f) {
    unsigned u;
    asm("cvt.rna.tf32.f32 %0, %1;" : "=r"(u) : "f"(f));
    return u;
}
__device__ __forceinline__ float ex2(float x) {
    float y;
    asm("ex2.approx.ftz.f32 %0, %1;" : "=f"(y) : "f"(x));
    return y;
}
__device__ __forceinline__ void mma_tf32(float c[4], unsigned a0, unsigned a1,
                                         unsigned a2, unsigned a3,
                                         unsigned b0, unsigned b1) {
    asm volatile(
        "mma.sync.aligned.m16n8k8.row.col.f32.tf32.tf32.f32 "
        "{%0,%1,%2,%3}, {%4,%5,%6,%7}, {%8,%9}, {%0,%1,%2,%3};"
        : "+f"(c[0]), "+f"(c[1]), "+f"(c[2]), "+f"(c[3])
        : "r"(a0), "r"(a1), "r"(a2), "r"(a3), "r"(b0), "r"(b1));
}
__device__ __forceinline__ void cp16(void* smem, const void* gmem) {
    unsigned sa = (unsigned)__cvta_generic_to_shared(smem);
    asm volatile("cp.async.cg.shared.global [%0], [%1], 16;" :: "r"(sa), "l"(gmem));
}
#define CP_COMMIT() asm volatile("cp.async.commit_group;")
#define CP_WAIT0()  asm volatile("cp.async.wait_group 0;")

// ---------------------------------------------------------------------------
// Kernel 1: QKV projection, tf32 mma.  grid (128, 3), block 256 (8 warps).
// M-tile 64.  Warp (wid): m0=(wid>>1)*16, n-half=(wid&1)*32.
// K-chunk 16, double-buffered smem, register prefetch, 1 sync/chunk.
// Output stored tf32-rounded (consumed by attention MMAs as-is).
// ---------------------------------------------------------------------------
__global__ __launch_bounds__(256) void proj_mma_kernel(
    const float* __restrict__ x,
    const float* __restrict__ Wq, const float* __restrict__ bq,
    const float* __restrict__ Wk, const float* __restrict__ bk,
    const float* __restrict__ Wv, const float* __restrict__ bv)
{
    __shared__ unsigned As[2][64][20];
    __shared__ unsigned Ws[2][64][20];

    const float* W;
    const float* bias;
    float* out;
    if (blockIdx.y == 0)      { W = Wq; bias = bq; out = g_q; }
    else if (blockIdx.y == 1) { W = Wk; bias = bk; out = g_k; }
    else                      { W = Wv; bias = bv; out = g_v; }

    const int row0 = blockIdx.x * 64;
    const int tid  = threadIdx.x;
    const int wid  = tid >> 5;
    const int l    = tid & 31;
    const int g    = l >> 2;
    const int tg   = l & 3;
    const int m0   = (wid >> 1) * 16;
    const int nb   = (wid & 1) * 32;      // col base (4 n-frags of 8)

    const int r = tid >> 2;               // load row 0..63
    const int c = (tid & 3) * 4;          // col offset in 16-chunk

    float acc[4][4];
#pragma unroll
    for (int n = 0; n < 4; n++)
#pragma unroll
        for (int i = 0; i < 4; i++) acc[n][i] = 0.0f;

    float4 xa = *(const float4*)(x + (size_t)(row0 + r) * EE + c);
    float4 wa = *(const float4*)(W + (size_t)r * EE + c);
    {
        As[0][r][c+0]=f2tf32(xa.x); As[0][r][c+1]=f2tf32(xa.y);
        As[0][r][c+2]=f2tf32(xa.z); As[0][r][c+3]=f2tf32(xa.w);
        Ws[0][r][c+0]=f2tf32(wa.x); Ws[0][r][c+1]=f2tf32(wa.y);
        Ws[0][r][c+2]=f2tf32(wa.z); Ws[0][r][c+3]=f2tf32(wa.w);
    }
    __syncthreads();

    for (int kc = 0; kc < 64; kc++) {
        const int buf = kc & 1;
        if (kc + 1 < 64) {
            xa = *(const float4*)(x + (size_t)(row0 + r) * EE + (kc+1)*16 + c);
            wa = *(const float4*)(W + (size_t)r * EE + (kc+1)*16 + c);
        }
#pragma unroll
        for (int k8 = 0; k8 < 16; k8 += 8) {
            unsigned a0 = As[buf][m0 + g    ][tg     + k8];
            unsigned a1 = As[buf][m0 + g + 8][tg     + k8];
            unsigned a2 = As[buf][m0 + g    ][tg + 4 + k8];
            unsigned a3 = As[buf][m0 + g + 8][tg + 4 + k8];
#pragma unroll
            for (int n0 = 0; n0 < 4; n0++) {
                unsigned b0 = Ws[buf][nb + n0*8 + g][tg     + k8];
                unsigned b1 = Ws[buf][nb + n0*8 + g][tg + 4 + k8];
                mma_tf32(acc[n0], a0, a1, a2, a3, b0, b1);
            }
        }
        if (kc + 1 < 64) {
            const int nbuf = 1 - buf;
            As[nbuf][r][c+0]=f2tf32(xa.x); As[nbuf][r][c+1]=f2tf32(xa.y);
            As[nbuf][r][c+2]=f2tf32(xa.z); As[nbuf][r][c+3]=f2tf32(xa.w);
            Ws[nbuf][r][c+0]=f2tf32(wa.x); Ws[nbuf][r][c+1]=f2tf32(wa.y);
            Ws[nbuf][r][c+2]=f2tf32(wa.z); Ws[nbuf][r][c+3]=f2tf32(wa.w);
        }
        __syncthreads();
    }

#pragma unroll
    for (int n0 = 0; n0 < 4; n0++) {
        int col = nb + n0*8 + 2*tg;
        float b0 = bias[col], b1 = bias[col+1];
        float2 v0, v1;
        v0.x = __uint_as_float(f2tf32(acc[n0][0] + b0));
        v0.y = __uint_as_float(f2tf32(acc[n0][1] + b1));
        v1.x = __uint_as_float(f2tf32(acc[n0][2] + b0));
        v1.y = __uint_as_float(f2tf32(acc[n0][3] + b1));
        *(float2*)(out + (size_t)(row0 + m0 + g    ) * HH + col) = v0;
        *(float2*)(out + (size_t)(row0 + m0 + g + 8) * HH + col) = v1;
    }
}

// ---------------------------------------------------------------------------
// Kernel 2: causal flash attention, tf32 mma.
// grid = (T/64, B) = (32,4), block 256 (8 warps).
// Warp wid: m-tile mt = wid&3 (16 query rows), stream s = wid>>2.
// Stream s processes KV tiles s, s+2, ... (64 keys each); merged at end.
// smem pitch 68 floats (== 4 mod 32 -> conflict-free fragment access).
// ---------------------------------------------------------------------------
#define PITCH 68
#define QS_OFF 0                         // 64*68       = 4352
#define KS_OFF 4352                      // 2*64*68     = 8704
#define VS_OFF 13056                     // 2*64*68     = 8704
#define PS_OFF 21760                     // 8*16*68     = 8704
#define MO_OFF 30464                     // 4*16*68     = 4352
#define ML_OFF 34816                     // 4*32        = 128
#define SM_FLOATS 34944                  // *4 = 139776 bytes
#define SCL 0.18033688011112042f         // (1/8) * log2(e)

__global__ __launch_bounds__(256) void attn_kernel(float* __restrict__ out)
{
    extern __shared__ float sm[];

    const int b   = blockIdx.y;
    const int qt0 = (gridDim.x - 1 - blockIdx.x) * 64;   // heavy blocks first
    const int tid = threadIdx.x;
    const int wid = tid >> 5;
    const int l   = tid & 31;
    const int g   = l >> 2;
    const int tg  = l & 3;
    const int mt  = wid & 3;
    const int s   = wid >> 2;

    const int ntiles = qt0 / 64 + 1;
    const int nsuper = (ntiles + 1) >> 1;

    const float* kbase = g_k + (size_t)b * TT * HH;
    const float* vbase = g_v + (size_t)b * TT * HH;

    // Q tile load via cp.async (grouped with first K/V loads)
    {
        const float* qsrc = g_q + ((size_t)b * TT + qt0) * HH;
#pragma unroll
        for (int t = 0; t < 4; t++) {
            int cid = tid + t * 256;          // 0..1023
            int row = cid >> 4, c16 = cid & 15;
            cp16(sm + QS_OFF + row * PITCH + c16 * 4, qsrc + row * HH + c16 * 4);
        }
    }

    unsigned qreg[8][4];
    float o[8][4];
    float m_lo = -INFINITY, m_hi = -INFINITY, l_lo = 0.f, l_hi = 0.f;
#pragma unroll
    for (int n = 0; n < 8; n++)
#pragma unroll
        for (int i = 0; i < 4; i++) o[n][i] = 0.0f;

    float* Ps = sm + PS_OFF + wid * (16 * PITCH);

    for (int it = 0; it < nsuper; it++) {
        __syncthreads();    // buffers free (no-op first iter)
        // load K/V tiles 2*it and 2*it+1 into stream buffers
#pragma unroll
        for (int t = 0; t < 16; t++) {
            int cidf = tid + t * 256;         // 0..4095
            int sel  = cidf >> 10;            // 0:K s0 1:K s1 2:V s0 3:V s1
            int cid  = cidf & 1023;
            int row  = cid >> 4, c16 = cid & 15;
            int kt   = 2 * it + (sel & 1);
            if (kt < ntiles) {
                const float* src = ((sel >> 1) ? vbase : kbase)
                                   + ((size_t)kt * 64 + row) * HH + c16 * 4;
                float* dst = sm + ((sel >> 1) ? VS_OFF : KS_OFF)
                             + (sel & 1) * (64 * PITCH) + row * PITCH + c16 * 4;
                cp16(dst, src);
            }
        }
        CP_COMMIT();
        CP_WAIT0();
        __syncthreads();

        if (it == 0) {       // Q fragments -> registers (once)
#pragma unroll
            for (int k8 = 0; k8 < 8; k8++) {
                const float* Qb = sm + QS_OFF + k8 * 8;
                qreg[k8][0] = __float_as_uint(Qb[(mt*16 + g    ) * PITCH + tg    ]);
                qreg[k8][1] = __float_as_uint(Qb[(mt*16 + g + 8) * PITCH + tg    ]);
                qreg[k8][2] = __float_as_uint(Qb[(mt*16 + g    ) * PITCH + tg + 4]);
                qreg[k8][3] = __float_as_uint(Qb[(mt*16 + g + 8) * PITCH + tg + 4]);
            }
        }

        const int kt = 2 * it + s;
        if (kt < ntiles) {
            const int k0 = kt * 64;
            const float* Kb = sm + KS_OFF + s * (64 * PITCH);
            const float* Vb = sm + VS_OFF + s * (64 * PITCH);

            // ---- S = Q . K^T ----
            float sc[8][4];
#pragma unroll
            for (int n = 0; n < 8; n++)
#pragma unroll
                for (int i = 0; i < 4; i++) sc[n][i] = 0.0f;
#pragma unroll
            for (int k8 = 0; k8 < 8; k8++) {
#pragma unroll
                for (int n0 = 0; n0 < 8; n0++) {
                    unsigned b0 = __float_as_uint(Kb[(n0*8 + g) * PITCH + k8*8 + tg    ]);
                    unsigned b1 = __float_as_uint(Kb[(n0*8 + g) * PITCH + k8*8 + tg + 4]);
                    mma_tf32(sc[n0], qreg[k8][0], qreg[k8][1], qreg[k8][2], qreg[k8][3], b0, b1);
                }
            }

            // ---- masked online softmax (log2 domain) ----
            const int t_lo = qt0 + mt*16 + g;
            const int t_hi = t_lo + 8;
            float mx_lo = -INFINITY, mx_hi = -INFINITY;
            float u[8][4];
#pragma unroll
            for (int n0 = 0; n0 < 8; n0++) {
                int c0 = k0 + n0*8 + 2*tg, c1 = c0 + 1;
                u[n0][0] = (c0 <= t_lo) ? sc[n0][0] * SCL : -INFINITY;
                u[n0][1] = (c1 <= t_lo) ? sc[n0][1] * SCL : -INFINITY;
                u[n0][2] = (c0 <= t_hi) ? sc[n0][2] * SCL : -INFINITY;
                u[n0][3] = (c1 <= t_hi) ? sc[n0][3] * SCL : -INFINITY;
                mx_lo = fmaxf(mx_lo, fmaxf(u[n0][0], u[n0][1]));
                mx_hi = fmaxf(mx_hi, fmaxf(u[n0][2], u[n0][3]));
            }
            mx_lo = fmaxf(mx_lo, __shfl_xor_sync(0xffffffffu, mx_lo, 1));
            mx_lo = fmaxf(mx_lo, __shfl_xor_sync(0xffffffffu, mx_lo, 2));
            mx_hi = fmaxf(mx_hi, __shfl_xor_sync(0xffffffffu, mx_hi, 1));
            mx_hi = fmaxf(mx_hi, __shfl_xor_sync(0xffffffffu, mx_hi, 2));
            float mn_lo = fmaxf(m_lo, mx_lo);
            float mn_hi = fmaxf(m_hi, mx_hi);
            float f_lo = ex2(m_lo - mn_lo);
            float f_hi = ex2(m_hi - mn_hi);

            float sum_lo = 0.f, sum_hi = 0.f;
#pragma unroll
            for (int n0 = 0; n0 < 8; n0++) {
                float p0 = ex2(u[n0][0] - mn_lo);
                float p1 = ex2(u[n0][1] - mn_lo);
                float p2 = ex2(u[n0][2] - mn_hi);
                float p3 = ex2(u[n0][3] - mn_hi);
                sum_lo += p0 + p1;
                sum_hi += p2 + p3;
                float2 w0, w1;    // tf32-rounded P into smem
                w0.x = __uint_as_float(f2tf32(p0)); w0.y = __uint_as_float(f2tf32(p1));
                w1.x = __uint_as_float(f2tf32(p2)); w1.y = __uint_as_float(f2tf32(p3));
                *(float2*)(Ps + (g    ) * PITCH + n0*8 + 2*tg) = w0;
                *(float2*)(Ps + (g + 8) * PITCH + n0*8 + 2*tg) = w1;
            }
            sum_lo += __shfl_xor_sync(0xffffffffu, sum_lo, 1);
            sum_lo += __shfl_xor_sync(0xffffffffu, sum_lo, 2);
            sum_hi += __shfl_xor_sync(0xffffffffu, sum_hi, 1);
            sum_hi += __shfl_xor_sync(0xffffffffu, sum_hi, 2);
            l_lo = l_lo * f_lo + sum_lo;
            l_hi = l_hi * f_hi + sum_hi;
            m_lo = mn_lo; m_hi = mn_hi;
#pragma unroll
            for (int n0 = 0; n0 < 8; n0++) {
                o[n0][0] *= f_lo; o[n0][1] *= f_lo;
                o[n0][2] *= f_hi; o[n0][3] *= f_hi;
            }
            __syncwarp();

            // ---- O += P . V ----
#pragma unroll
            for (int k8 = 0; k8 < 8; k8++) {
                unsigned a0 = __float_as_uint(Ps[(g    ) * PITCH + k8*8 + tg    ]);
                unsigned a1 = __float_as_uint(Ps[(g + 8) * PITCH + k8*8 + tg    ]);
                unsigned a2 = __float_as_uint(Ps[(g    ) * PITCH + k8*8 + tg + 4]);
                unsigned a3 = __float_as_uint(Ps[(g + 8) * PITCH + k8*8 + tg + 4]);
#pragma unroll
                for (int n0 = 0; n0 < 8; n0++) {
                    unsigned b0 = __float_as_uint(Vb[(k8*8 + tg    ) * PITCH + n0*8 + g]);
                    unsigned b1 = __float_as_uint(Vb[(k8*8 + tg + 4) * PITCH + n0*8 + g]);
                    mma_tf32(o[n0], a0, a1, a2, a3, b0, b1);
                }
            }
            __syncwarp();   // Ps reads done before next tile overwrites
        }
    }

    // ---- merge streams (s==1 publishes, s==0 combines & writes) ----
    __syncthreads();
    float* Om = sm + MO_OFF + mt * (16 * PITCH);
    float* Ml = sm + ML_OFF + mt * 32;
    if (s == 1) {
#pragma unroll
        for (int n0 = 0; n0 < 8; n0++) {
            *(float2*)(Om + (g    ) * PITCH + n0*8 + 2*tg) = make_float2(o[n0][0], o[n0][1]);
            *(float2*)(Om + (g + 8) * PITCH + n0*8 + 2*tg) = make_float2(o[n0][2], o[n0][3]);
        }
        Ml[g] = m_lo; Ml[g + 8] = m_hi;
        Ml[16 + g] = l_lo; Ml[16 + 8 + g] = l_hi;
    }
    __syncthreads();
    if (s == 0) {
        float m2_lo = Ml[g], m2_hi = Ml[g + 8];
        float l2_lo = Ml[16 + g], l2_hi = Ml[16 + 8 + g];
        float mf_lo = fmaxf(m_lo, m2_lo), mf_hi = fmaxf(m_hi, m2_hi);
        float a_lo = ex2(m_lo - mf_lo), b_lo = ex2(m2_lo - mf_lo);
        float a_hi = ex2(m_hi - mf_hi), b_hi = ex2(m2_hi - mf_hi);
        float inv_lo = 1.0f / (l_lo * a_lo + l2_lo * b_lo);
        float inv_hi = 1.0f / (l_hi * a_hi + l2_hi * b_hi);
        const int t_lo = qt0 + mt*16 + g;
#pragma unroll
        for (int n0 = 0; n0 < 8; n0++) {
            float2 o2l = *(float2*)(Om + (g    ) * PITCH + n0*8 + 2*tg);
            float2 o2h = *(float2*)(Om + (g + 8) * PITCH + n0*8 + 2*tg);
            float2 r0, r1;
            r0.x = (o[n0][0] * a_lo + o2l.x * b_lo) * inv_lo;
            r0.y = (o[n0][1] * a_lo + o2l.y * b_lo) * inv_lo;
            r1.x = (o[n0][2] * a_hi + o2h.x * b_hi) * inv_hi;
            r1.y = (o[n0][3] * a_hi + o2h.y * b_hi) * inv_hi;
            *(float2*)(out + ((size_t)b * TT + t_lo    ) * HH + n0*8 + 2*tg) = r0;
            *(float2*)(out + ((size_t)b * TT + t_lo + 8) * HH + n0*8 + 2*tg) = r1;
        }
    }
}

// ---------------------------------------------------------------------------
extern "C" void kernel_launch(void* const* d_in, const int* in_sizes, int n_in,
                              void* d_out, int out_size)
{
    const float* x  = (const float*)d_in[0];
    const float* Wq = (const float*)d_in[1];
    const float* bq = (const float*)d_in[2];
    const float* Wk = (const float*)d_in[3];
    const float* bk = (const float*)d_in[4];
    const float* Wv = (const float*)d_in[5];
    const float* bv = (const float*)d_in[6];
    float* out = (float*)d_out;

    dim3 pgrid(MM / 64, 3);
    proj_mma_kernel<<<pgrid, 256>>>(x, Wq, bq, Wk, bk, Wv, bv);

    const int smem_bytes = SM_FLOATS * sizeof(float);   // 139776
    cudaFuncSetAttribute(attn_kernel, cudaFuncAttributeMaxDynamicSharedMemorySize, smem_bytes);
    dim3 agrid(TT / 64, BB);
    attn_kernel<<<agrid, 256, smem_bytes>>>(out);
}

// round 5
// speedup vs baseline: 3.3815x; 1.3696x over previous
#include <cuda_runtime.h>
#include <math.h>

#define BB 4
#define TT 2048
#define EE 1024
#define HH 64
#define MM (BB*TT)

// device scratch (module statics: allocation-free)
__device__ float g_q[MM*HH];
__device__ float g_k[MM*HH];
__device__ float g_v[MM*HH];
// split-KV partials: pidx = (b*32 + qtile)*4 + chunk
__device__ float g_po[512*64*64];     // unnormalized O numerators
__device__ float g_ml[512*64*2];      // per-row (m_log2, l)

__device__ __forceinline__ unsigned f2tf32(float f) {
    unsigned u;
    asm("cvt.rna.tf32.f32 %0, %1;" : "=r"(u) : "f"(f));
    return u;
}
__device__ __forceinline__ float ex2(float x) {
    float y;
    asm("ex2.approx.ftz.f32 %0, %1;" : "=f"(y) : "f"(x));
    return y;
}
__device__ __forceinline__ void mma_tf32(float c[4], unsigned a0, unsigned a1,
                                         unsigned a2, unsigned a3,
                                         unsigned b0, unsigned b1) {
    asm volatile(
        "mma.sync.aligned.m16n8k8.row.col.f32.tf32.tf32.f32 "
        "{%0,%1,%2,%3}, {%4,%5,%6,%7}, {%8,%9}, {%0,%1,%2,%3};"
        : "+f"(c[0]), "+f"(c[1]), "+f"(c[2]), "+f"(c[3])
        : "r"(a0), "r"(a1), "r"(a2), "r"(a3), "r"(b0), "r"(b1));
}
__device__ __forceinline__ void cp16(void* smem, const void* gmem) {
    unsigned sa = (unsigned)__cvta_generic_to_shared(smem);
    asm volatile("cp.async.cg.shared.global [%0], [%1], 16;" :: "r"(sa), "l"(gmem));
}
#define CP_COMMIT() asm volatile("cp.async.commit_group;")
#define CP_WAIT0()  asm volatile("cp.async.wait_group 0;")
#define CP_WAIT1()  asm volatile("cp.async.wait_group 1;")

// ---------------------------------------------------------------------------
// Kernel 1: FUSED QKV projection, tf32 mma, cp.async double-buffered.
// grid = 128 blocks (64 rows each), block 256 (8 warps).
// Warp: mt = wid&3 -> rows mt*16.., nh = wid>>2 -> cols nh*32.. (4 n-frags).
// Each block computes Q, K, V for its rows (X read once).
// Outputs stored tf32-rounded.
// ---------------------------------------------------------------------------
__global__ __launch_bounds__(256) void proj_kernel(
    const float* __restrict__ x,
    const float* __restrict__ Wq, const float* __restrict__ bq,
    const float* __restrict__ Wk, const float* __restrict__ bk,
    const float* __restrict__ Wv, const float* __restrict__ bv)
{
    __shared__ __align__(16) float Xs[2][64][20];
    __shared__ __align__(16) float Ws3[3][2][64][20];

    const int row0 = blockIdx.x * 64;
    const int tid = threadIdx.x;
    const int wid = tid >> 5, l = tid & 31, g = l >> 2, tg = l & 3;
    const int m0 = (wid & 3) * 16;
    const int nb = (wid >> 2) * 32;

    const int lr = tid >> 2;        // 0..63
    const int lc = (tid & 3) * 4;   // 0,4,8,12

    const float* Wm[3] = {Wq, Wk, Wv};

    float acc[3][4][4];
#pragma unroll
    for (int mat = 0; mat < 3; mat++)
#pragma unroll
        for (int n = 0; n < 4; n++)
#pragma unroll
            for (int i = 0; i < 4; i++) acc[mat][n][i] = 0.0f;

    // prefetch chunk 0
    cp16(&Xs[0][lr][lc], x + (size_t)(row0 + lr) * EE + lc);
#pragma unroll
    for (int mat = 0; mat < 3; mat++)
        cp16(&Ws3[mat][0][lr][lc], Wm[mat] + (size_t)lr * EE + lc);
    CP_COMMIT();

    for (int kc = 0; kc < 64; kc++) {
        const int buf = kc & 1;
        if (kc + 1 < 64) {
            const int nbuf = buf ^ 1, off = (kc + 1) * 16;
            cp16(&Xs[nbuf][lr][lc], x + (size_t)(row0 + lr) * EE + off + lc);
#pragma unroll
            for (int mat = 0; mat < 3; mat++)
                cp16(&Ws3[mat][nbuf][lr][lc], Wm[mat] + (size_t)lr * EE + off + lc);
            CP_COMMIT();
            CP_WAIT1();
        } else {
            CP_WAIT0();
        }
        __syncthreads();

#pragma unroll
        for (int k8 = 0; k8 < 16; k8 += 8) {
            unsigned a0 = f2tf32(Xs[buf][m0 + g    ][tg     + k8]);
            unsigned a1 = f2tf32(Xs[buf][m0 + g + 8][tg     + k8]);
            unsigned a2 = f2tf32(Xs[buf][m0 + g    ][tg + 4 + k8]);
            unsigned a3 = f2tf32(Xs[buf][m0 + g + 8][tg + 4 + k8]);
#pragma unroll
            for (int mat = 0; mat < 3; mat++) {
#pragma unroll
                for (int n0 = 0; n0 < 4; n0++) {
                    int rw = nb + n0 * 8 + g;
                    unsigned b0 = f2tf32(Ws3[mat][buf][rw][tg     + k8]);
                    unsigned b1 = f2tf32(Ws3[mat][buf][rw][tg + 4 + k8]);
                    mma_tf32(acc[mat][n0], a0, a1, a2, a3, b0, b1);
                }
            }
        }
        __syncthreads();
    }

    const float* bs[3] = {bq, bk, bv};
    float* outs[3] = {g_q, g_k, g_v};
#pragma unroll
    for (int mat = 0; mat < 3; mat++) {
#pragma unroll
        for (int n0 = 0; n0 < 4; n0++) {
            int col = nb + n0 * 8 + 2 * tg;
            float b0 = bs[mat][col], b1 = bs[mat][col + 1];
            float2 v0, v1;
            v0.x = __uint_as_float(f2tf32(acc[mat][n0][0] + b0));
            v0.y = __uint_as_float(f2tf32(acc[mat][n0][1] + b1));
            v1.x = __uint_as_float(f2tf32(acc[mat][n0][2] + b0));
            v1.y = __uint_as_float(f2tf32(acc[mat][n0][3] + b1));
            *(float2*)(outs[mat] + (size_t)(row0 + m0 + g    ) * HH + col) = v0;
            *(float2*)(outs[mat] + (size_t)(row0 + m0 + g + 8) * HH + col) = v1;
        }
    }
}

// ---------------------------------------------------------------------------
// Kernel 2: causal flash attention, tf32 mma, split-KV + pipelined cp.async.
// Work unit: (b, q-tile qi of 64 rows, chunk ch of <=8 KV tiles of 64 keys).
// grid = (80, 4): 80 = sum over qi of ceil((qi+1)/8), heavy qi first.
// 8 warps: mt = wid&3 (16 rows), s = wid>>2 (2 KV streams within chunk).
// K/V double-buffered across supersteps.  Partials merged by merge_kernel.
// ---------------------------------------------------------------------------
#define PITCH 68
#define TILE_F (64*PITCH)                    // 4352 floats
#define QS_OFF 0
#define KS_OFF TILE_F                        // 4352   (4 tiles: s*2+buf)
#define VS_OFF (KS_OFF + 4*TILE_F)           // 21760  (4 tiles)
#define PS_OFF (VS_OFF + 4*TILE_F)           // 39168  (8 warps x 16 x PITCH)
#define SM_FLOATS (PS_OFF + 8*16*PITCH)      // 47872 -> 191488 bytes
#define SCL 0.18033688011112042f             // (1/8) * log2(e)

__device__ __forceinline__ void attn_prefetch(
    float* sm, const float* kbase, const float* vbase,
    int tid, int tbase, int nt, int j)
{
    const int buf = j & 1;
#pragma unroll
    for (int t = 0; t < 16; t++) {
        int cidf = tid + t * 256;          // 0..4095
        int sel  = cidf >> 10;             // 0:K s0  1:K s1  2:V s0  3:V s1
        int cid  = cidf & 1023;
        int row  = cid >> 4, c16 = cid & 15;
        int jt   = 2 * j + (sel & 1);
        if (jt < nt) {
            const float* src = ((sel >> 1) ? vbase : kbase)
                               + ((size_t)((tbase + jt) * 64 + row)) * HH + c16 * 4;
            float* dst = sm + ((sel >> 1) ? VS_OFF : KS_OFF)
                         + ((sel & 1) * 2 + buf) * TILE_F + row * PITCH + c16 * 4;
            cp16(dst, src);
        }
    }
}

__global__ __launch_bounds__(256) void attn_kernel(float* __restrict__ out)
{
    extern __shared__ float sm[];

    const int b   = blockIdx.y;
    const int tid = threadIdx.x;
    const int wid = tid >> 5, l = tid & 31, g = l >> 2, tg = l & 3;
    const int mt  = wid & 3;
    const int s   = wid >> 2;

    // worklist decode: heavy q-tiles first
    int qi = 0, ch = 0;
    {
        int wl = blockIdx.x, acc = 0;
        for (int ii = 31; ii >= 0; ii--) {
            int nc = (ii + 8) >> 3;            // ceil((ii+1)/8)
            if (wl < acc + nc) { qi = ii; ch = wl - acc; break; }
            acc += nc;
        }
    }
    const int qt0    = qi * 64;
    const int ntiles = qi + 1;
    const int nch    = (qi + 8) >> 3;
    const int tbase  = ch * 8;
    int nt = ntiles - tbase; if (nt > 8) nt = 8;
    const int ns = (nt + 1) >> 1;

    const float* kbase = g_k + (size_t)b * TT * HH;
    const float* vbase = g_v + (size_t)b * TT * HH;

    // group 0: Q tile + superstep 0
    {
        const float* qsrc = g_q + ((size_t)b * TT + qt0) * HH;
#pragma unroll
        for (int t = 0; t < 4; t++) {
            int cid = tid + t * 256;
            int row = cid >> 4, c16 = cid & 15;
            cp16(sm + QS_OFF + row * PITCH + c16 * 4, qsrc + row * HH + c16 * 4);
        }
        attn_prefetch(sm, kbase, vbase, tid, tbase, nt, 0);
        CP_COMMIT();
    }

    unsigned qreg[8][4];
    float o[8][4];
    float m_lo = -INFINITY, m_hi = -INFINITY, l_lo = 0.f, l_hi = 0.f;
#pragma unroll
    for (int n = 0; n < 8; n++)
#pragma unroll
        for (int i = 0; i < 4; i++) o[n][i] = 0.0f;

    float* Ps = sm + PS_OFF + wid * (16 * PITCH);

    for (int j = 0; j < ns; j++) {
        const int buf = j & 1;
        if (j + 1 < ns) {
            attn_prefetch(sm, kbase, vbase, tid, tbase, nt, j + 1);
            CP_COMMIT();
            CP_WAIT1();
        } else {
            CP_WAIT0();
        }
        __syncthreads();

        if (j == 0) {       // Q fragments -> registers (once)
#pragma unroll
            for (int k8 = 0; k8 < 8; k8++) {
                const float* Qb = sm + QS_OFF + k8 * 8;
                qreg[k8][0] = __float_as_uint(Qb[(mt*16 + g    ) * PITCH + tg    ]);
                qreg[k8][1] = __float_as_uint(Qb[(mt*16 + g + 8) * PITCH + tg    ]);
                qreg[k8][2] = __float_as_uint(Qb[(mt*16 + g    ) * PITCH + tg + 4]);
                qreg[k8][3] = __float_as_uint(Qb[(mt*16 + g + 8) * PITCH + tg + 4]);
            }
        }

        const int jt = 2 * j + s;
        if (jt < nt) {
            const int k0 = (tbase + jt) * 64;
            const float* Kb = sm + KS_OFF + (s * 2 + buf) * TILE_F;
            const float* Vb = sm + VS_OFF + (s * 2 + buf) * TILE_F;

            // ---- S = Q . K^T ----
            float sc[8][4];
#pragma unroll
            for (int n = 0; n < 8; n++)
#pragma unroll
                for (int i = 0; i < 4; i++) sc[n][i] = 0.0f;
#pragma unroll
            for (int k8 = 0; k8 < 8; k8++) {
#pragma unroll
                for (int n0 = 0; n0 < 8; n0++) {
                    unsigned b0 = __float_as_uint(Kb[(n0*8 + g) * PITCH + k8*8 + tg    ]);
                    unsigned b1 = __float_as_uint(Kb[(n0*8 + g) * PITCH + k8*8 + tg + 4]);
                    mma_tf32(sc[n0], qreg[k8][0], qreg[k8][1], qreg[k8][2], qreg[k8][3], b0, b1);
                }
            }

            // ---- masked online softmax (log2 domain) ----
            const int t_lo = qt0 + mt*16 + g;
            const int t_hi = t_lo + 8;
            float mx_lo = -INFINITY, mx_hi = -INFINITY;
            float u[8][4];
#pragma unroll
            for (int n0 = 0; n0 < 8; n0++) {
                int c0 = k0 + n0*8 + 2*tg, c1 = c0 + 1;
                u[n0][0] = (c0 <= t_lo) ? sc[n0][0] * SCL : -INFINITY;
                u[n0][1] = (c1 <= t_lo) ? sc[n0][1] * SCL : -INFINITY;
                u[n0][2] = (c0 <= t_hi) ? sc[n0][2] * SCL : -INFINITY;
                u[n0][3] = (c1 <= t_hi) ? sc[n0][3] * SCL : -INFINITY;
                mx_lo = fmaxf(mx_lo, fmaxf(u[n0][0], u[n0][1]));
                mx_hi = fmaxf(mx_hi, fmaxf(u[n0][2], u[n0][3]));
            }
            mx_lo = fmaxf(mx_lo, __shfl_xor_sync(0xffffffffu, mx_lo, 1));
            mx_lo = fmaxf(mx_lo, __shfl_xor_sync(0xffffffffu, mx_lo, 2));
            mx_hi = fmaxf(mx_hi, __shfl_xor_sync(0xffffffffu, mx_hi, 1));
            mx_hi = fmaxf(mx_hi, __shfl_xor_sync(0xffffffffu, mx_hi, 2));
            float mn_lo = fmaxf(m_lo, mx_lo);
            float mn_hi = fmaxf(m_hi, mx_hi);
            float f_lo = ex2(m_lo - mn_lo);
            float f_hi = ex2(m_hi - mn_hi);

            float sum_lo = 0.f, sum_hi = 0.f;
#pragma unroll
            for (int n0 = 0; n0 < 8; n0++) {
                float p0 = ex2(u[n0][0] - mn_lo);
                float p1 = ex2(u[n0][1] - mn_lo);
                float p2 = ex2(u[n0][2] - mn_hi);
                float p3 = ex2(u[n0][3] - mn_hi);
                sum_lo += p0 + p1;
                sum_hi += p2 + p3;
                float2 w0, w1;
                w0.x = __uint_as_float(f2tf32(p0)); w0.y = __uint_as_float(f2tf32(p1));
                w1.x = __uint_as_float(f2tf32(p2)); w1.y = __uint_as_float(f2tf32(p3));
                *(float2*)(Ps + (g    ) * PITCH + n0*8 + 2*tg) = w0;
                *(float2*)(Ps + (g + 8) * PITCH + n0*8 + 2*tg) = w1;
            }
            sum_lo += __shfl_xor_sync(0xffffffffu, sum_lo, 1);
            sum_lo += __shfl_xor_sync(0xffffffffu, sum_lo, 2);
            sum_hi += __shfl_xor_sync(0xffffffffu, sum_hi, 1);
            sum_hi += __shfl_xor_sync(0xffffffffu, sum_hi, 2);
            l_lo = l_lo * f_lo + sum_lo;
            l_hi = l_hi * f_hi + sum_hi;
            m_lo = mn_lo; m_hi = mn_hi;
#pragma unroll
            for (int n0 = 0; n0 < 8; n0++) {
                o[n0][0] *= f_lo; o[n0][1] *= f_lo;
                o[n0][2] *= f_hi; o[n0][3] *= f_hi;
            }
            __syncwarp();

            // ---- O += P . V ----
#pragma unroll
            for (int k8 = 0; k8 < 8; k8++) {
                unsigned a0 = __float_as_uint(Ps[(g    ) * PITCH + k8*8 + tg    ]);
                unsigned a1 = __float_as_uint(Ps[(g + 8) * PITCH + k8*8 + tg    ]);
                unsigned a2 = __float_as_uint(Ps[(g    ) * PITCH + k8*8 + tg + 4]);
                unsigned a3 = __float_as_uint(Ps[(g + 8) * PITCH + k8*8 + tg + 4]);
#pragma unroll
                for (int n0 = 0; n0 < 8; n0++) {
                    unsigned b0 = __float_as_uint(Vb[(k8*8 + tg    ) * PITCH + n0*8 + g]);
                    unsigned b1 = __float_as_uint(Vb[(k8*8 + tg + 4) * PITCH + n0*8 + g]);
                    mma_tf32(o[n0], a0, a1, a2, a3, b0, b1);
                }
            }
        }
        __syncthreads();   // all reads of buf done before it is re-prefetched
    }

    // ---- merge the two streams; write out or partials ----
    float* Om = sm + PS_OFF + mt * (16 * PITCH);           // overlays P (warps 0..3)
    float* Ml = sm + PS_OFF + 4 * (16 * PITCH) + mt * 32;  // overlays P (warps 4..7)
    if (s == 1) {
#pragma unroll
        for (int n0 = 0; n0 < 8; n0++) {
            *(float2*)(Om + (g    ) * PITCH + n0*8 + 2*tg) = make_float2(o[n0][0], o[n0][1]);
            *(float2*)(Om + (g + 8) * PITCH + n0*8 + 2*tg) = make_float2(o[n0][2], o[n0][3]);
        }
        Ml[g] = m_lo; Ml[g + 8] = m_hi;
        Ml[16 + g] = l_lo; Ml[16 + 8 + g] = l_hi;
    }
    __syncthreads();
    if (s == 0) {
        float m2_lo = Ml[g], m2_hi = Ml[g + 8];
        float l2_lo = Ml[16 + g], l2_hi = Ml[16 + 8 + g];
        float mf_lo = fmaxf(m_lo, m2_lo), mf_hi = fmaxf(m_hi, m2_hi);
        float a_lo = ex2(m_lo - mf_lo), b_lo = ex2(m2_lo - mf_lo);
        float a_hi = ex2(m_hi - mf_hi), b_hi = ex2(m2_hi - mf_hi);
        float lm_lo = l_lo * a_lo + l2_lo * b_lo;
        float lm_hi = l_hi * a_hi + l2_hi * b_hi;
        const int r_lo = mt*16 + g, r_hi = r_lo + 8;

        if (nch == 1) {
            float inv_lo = 1.0f / lm_lo, inv_hi = 1.0f / lm_hi;
#pragma unroll
            for (int n0 = 0; n0 < 8; n0++) {
                float2 o2l = *(float2*)(Om + (g    ) * PITCH + n0*8 + 2*tg);
                float2 o2h = *(float2*)(Om + (g + 8) * PITCH + n0*8 + 2*tg);
                float2 r0, r1;
                r0.x = (o[n0][0] * a_lo + o2l.x * b_lo) * inv_lo;
                r0.y = (o[n0][1] * a_lo + o2l.y * b_lo) * inv_lo;
                r1.x = (o[n0][2] * a_hi + o2h.x * b_hi) * inv_hi;
                r1.y = (o[n0][3] * a_hi + o2h.y * b_hi) * inv_hi;
                *(float2*)(out + ((size_t)b * TT + qt0 + r_lo) * HH + n0*8 + 2*tg) = r0;
                *(float2*)(out + ((size_t)b * TT + qt0 + r_hi) * HH + n0*8 + 2*tg) = r1;
            }
        } else {
            const int pidx = (b * 32 + qi) * 4 + ch;
            float* pod = g_po + (size_t)pidx * 4096;
#pragma unroll
            for (int n0 = 0; n0 < 8; n0++) {
                float2 o2l = *(float2*)(Om + (g    ) * PITCH + n0*8 + 2*tg);
                float2 o2h = *(float2*)(Om + (g + 8) * PITCH + n0*8 + 2*tg);
                float2 r0, r1;
                r0.x = o[n0][0] * a_lo + o2l.x * b_lo;
                r0.y = o[n0][1] * a_lo + o2l.y * b_lo;
                r1.x = o[n0][2] * a_hi + o2h.x * b_hi;
                r1.y = o[n0][3] * a_hi + o2h.y * b_hi;
                *(float2*)(pod + r_lo * 64 + n0*8 + 2*tg) = r0;
                *(float2*)(pod + r_hi * 64 + n0*8 + 2*tg) = r1;
            }
            if (tg == 0) {
                g_ml[pidx*128 + r_lo*2] = mf_lo; g_ml[pidx*128 + r_lo*2 + 1] = lm_lo;
                g_ml[pidx*128 + r_hi*2] = mf_hi; g_ml[pidx*128 + r_hi*2 + 1] = lm_hi;
            }
        }
    }
}

// ---------------------------------------------------------------------------
// Kernel 3: merge split-KV partials for q-tiles with >=2 chunks (qi >= 8).
// grid (24, 4), block 256: thread -> (row = tid/4, 16 cols).
// ---------------------------------------------------------------------------
__global__ __launch_bounds__(256) void merge_kernel(float* __restrict__ out)
{
    const int qi  = 8 + blockIdx.x;
    const int b   = blockIdx.y;
    const int nch = (qi + 8) >> 3;        // 2..4
    const int tid = threadIdx.x;
    const int r   = tid >> 2;
    const int cg  = (tid & 3) * 16;
    const int pbase = (b * 32 + qi) * 4;

    float mv[4], lv[4], e[4];
    float mf = -INFINITY;
    for (int c = 0; c < nch; c++) {
        mv[c] = g_ml[(pbase + c)*128 + r*2];
        lv[c] = g_ml[(pbase + c)*128 + r*2 + 1];
        mf = fmaxf(mf, mv[c]);
    }
    float wsum = 0.f;
    for (int c = 0; c < nch; c++) { e[c] = ex2(mv[c] - mf); wsum += lv[c] * e[c]; }
    float inv = 1.0f / wsum;

    size_t obase = ((size_t)b * TT + qi * 64 + r) * HH;
#pragma unroll
    for (int c4 = 0; c4 < 4; c4++) {
        float4 a = make_float4(0.f, 0.f, 0.f, 0.f);
        for (int c = 0; c < nch; c++) {
            const float4 p = *(const float4*)(g_po + (size_t)(pbase + c)*4096 + r*64 + cg + c4*4);
            a.x += e[c]*p.x; a.y += e[c]*p.y; a.z += e[c]*p.z; a.w += e[c]*p.w;
        }
        a.x *= inv; a.y *= inv; a.z *= inv; a.w *= inv;
        *(float4*)(out + obase + cg + c4*4) = a;
    }
}

// ---------------------------------------------------------------------------
extern "C" void kernel_launch(void* const* d_in, const int* in_sizes, int n_in,
                              void* d_out, int out_size)
{
    const float* x  = (const float*)d_in[0];
    const float* Wq = (const float*)d_in[1];
    const float* bq = (const float*)d_in[2];
    const float* Wk = (const float*)d_in[3];
    const float* bk = (const float*)d_in[4];
    const float* Wv = (const float*)d_in[5];
    const float* bv = (const float*)d_in[6];
    float* out = (float*)d_out;

    proj_kernel<<<MM / 64, 256>>>(x, Wq, bq, Wk, bk, Wv, bv);

    const int smem_bytes = SM_FLOATS * sizeof(float);   // 191488
    cudaFuncSetAttribute(attn_kernel, cudaFuncAttributeMaxDynamicSharedMemorySize, smem_bytes);
    attn_kernel<<<dim3(80, BB), 256, smem_bytes>>>(out);

    merge_kernel<<<dim3(24, BB), 256>>>(out);
}

// round 6
// speedup vs baseline: 3.6209x; 1.0708x over previous
#include <cuda_runtime.h>
#include <math.h>

#define BB 4
#define TT 2048
#define EE 1024
#define HH 64
#define MM (BB*TT)

// device scratch (module statics: allocation-free)
__device__ float g_q[MM*HH];
__device__ float g_k[MM*HH];
__device__ float g_v[MM*HH];
// split-KV partials: pidx = (b*32 + qtile)*4 + chunk
__device__ float g_po[512*64*64];
__device__ float g_ml[512*64*2];

__device__ __forceinline__ unsigned f2tf32(float f) {
    unsigned u;
    asm("cvt.rna.tf32.f32 %0, %1;" : "=r"(u) : "f"(f));
    return u;
}
__device__ __forceinline__ float ex2(float x) {
    float y;
    asm("ex2.approx.ftz.f32 %0, %1;" : "=f"(y) : "f"(x));
    return y;
}
__device__ __forceinline__ void mma_tf32(float c[4], unsigned a0, unsigned a1,
                                         unsigned a2, unsigned a3,
                                         unsigned b0, unsigned b1) {
    asm volatile(
        "mma.sync.aligned.m16n8k8.row.col.f32.tf32.tf32.f32 "
        "{%0,%1,%2,%3}, {%4,%5,%6,%7}, {%8,%9}, {%0,%1,%2,%3};"
        : "+f"(c[0]), "+f"(c[1]), "+f"(c[2]), "+f"(c[3])
        : "r"(a0), "r"(a1), "r"(a2), "r"(a3), "r"(b0), "r"(b1));
}
// ldmatrix x4 on 32-bit data: each float row segment = 2 b16 columns.
#define LDSM4(r0,r1,r2,r3,addr) \
    asm volatile("ldmatrix.sync.aligned.m8n8.x4.shared.b16 {%0,%1,%2,%3}, [%4];" \
                 : "=r"(r0), "=r"(r1), "=r"(r2), "=r"(r3) : "r"(addr))

__device__ __forceinline__ void cp16(void* smem, const void* gmem) {
    unsigned sa = (unsigned)__cvta_generic_to_shared(smem);
    asm volatile("cp.async.cg.shared.global [%0], [%1], 16;" :: "r"(sa), "l"(gmem));
}
#define CP_COMMIT() asm volatile("cp.async.commit_group;")
#define CP_WAIT0()  asm volatile("cp.async.wait_group 0;")
#define CP_WAIT1()  asm volatile("cp.async.wait_group 1;")

// ---------------------------------------------------------------------------
// Kernel 1: FUSED QKV projection, tf32 mma + ldmatrix.
// grid 128 (64 rows/block), block 256 (8 warps: 4 m-tiles x 2 n-halves).
// Loader converts fp32->tf32 once (LDG -> cvt -> STS), 2-stage smem ring,
// ONE __syncthreads per K-chunk of 16.  Compute loop: LDSM + MMA only.
// smem per stage: X[64][20] + 3x W[64][20]  (pitch 20 => LDSM conflict-free)
// ---------------------------------------------------------------------------
__global__ __launch_bounds__(256) void proj_kernel(
    const float* __restrict__ x,
    const float* __restrict__ Wq, const float* __restrict__ bq,
    const float* __restrict__ Wk, const float* __restrict__ bk,
    const float* __restrict__ Wv, const float* __restrict__ bv)
{
    __shared__ __align__(16) unsigned smp[2][4*1280];   // 40 KB

    const int row0 = blockIdx.x * 64;
    const int tid = threadIdx.x;
    const int wid = tid >> 5, l = tid & 31, tg = l & 3;
    const int m0 = (wid & 3) * 16;
    const int nb = (wid >> 2) * 32;

    // loader mapping: thread -> row 0..63, float4 column c4
    const int lrow = tid >> 2;
    const int lc4  = (tid & 3) * 4;

    const float* srcs[4];
    srcs[0] = x  + (size_t)(row0 + lrow) * EE + lc4;
    srcs[1] = Wq + (size_t)lrow * EE + lc4;
    srcs[2] = Wk + (size_t)lrow * EE + lc4;
    srcs[3] = Wv + (size_t)lrow * EE + lc4;

    float4 st[4];
#define LDGC(kc) { _Pragma("unroll") for (int a = 0; a < 4; a++) \
                       st[a] = *(const float4*)(srcs[a] + (kc)*16); }
#define STSC(kc) { _Pragma("unroll") for (int a = 0; a < 4; a++) { \
                       uint4 u; u.x=f2tf32(st[a].x); u.y=f2tf32(st[a].y); \
                       u.z=f2tf32(st[a].z); u.w=f2tf32(st[a].w); \
                       *(uint4*)&smp[(kc)&1][a*1280 + lrow*20 + lc4] = u; } }

    float acc[3][4][4];
#pragma unroll
    for (int mat = 0; mat < 3; mat++)
#pragma unroll
        for (int n = 0; n < 4; n++)
#pragma unroll
            for (int i = 0; i < 4; i++) acc[mat][n][i] = 0.0f;

    const unsigned sb = (unsigned)__cvta_generic_to_shared(&smp[0][0]);
    // A fragment address (per-thread, within stage), bytes:
    const unsigned aoff = ((m0 + (l & 15)) * 20 + ((l & 16) >> 2)) * 4;
    // B fragment address (covers n0 pair via x4), bytes:
    const unsigned boff = ((nb + (l & 7) + ((l & 16) >> 1)) * 20 + ((l & 8) >> 1)) * 4;

    // prologue: chunk0 -> smem, chunk1 -> regs
    LDGC(0); STSC(0);
    LDGC(1);
    __syncthreads();

    for (int kc = 0; kc < 64; kc++) {
        if (kc + 1 < 64) {
            STSC(kc + 1);
            if (kc + 2 < 64) LDGC(kc + 2);
        }
        const unsigned stg = sb + (kc & 1) * 20480;
#pragma unroll
        for (int k8 = 0; k8 < 16; k8 += 8) {
            unsigned a0, a1, a2, a3;
            LDSM4(a0, a1, a2, a3, stg + aoff + k8 * 4);
#pragma unroll
            for (int mat = 0; mat < 3; mat++) {
#pragma unroll
                for (int n0p = 0; n0p < 2; n0p++) {
                    unsigned b0, b1, b2, b3;
                    LDSM4(b0, b1, b2, b3,
                          stg + 5120 + mat * 5120 + boff + n0p * 1280 + k8 * 4);
                    mma_tf32(acc[mat][n0p*2    ], a0, a1, a2, a3, b0, b1);
                    mma_tf32(acc[mat][n0p*2 + 1], a0, a1, a2, a3, b2, b3);
                }
            }
        }
        __syncthreads();
    }

    const int g = l >> 2;
    const float* bs[3] = {bq, bk, bv};
    float* outs[3] = {g_q, g_k, g_v};
#pragma unroll
    for (int mat = 0; mat < 3; mat++) {
#pragma unroll
        for (int n0 = 0; n0 < 4; n0++) {
            int col = nb + n0 * 8 + 2 * tg;
            float b0 = bs[mat][col], b1 = bs[mat][col + 1];
            float2 v0, v1;
            v0.x = __uint_as_float(f2tf32(acc[mat][n0][0] + b0));
            v0.y = __uint_as_float(f2tf32(acc[mat][n0][1] + b1));
            v1.x = __uint_as_float(f2tf32(acc[mat][n0][2] + b0));
            v1.y = __uint_as_float(f2tf32(acc[mat][n0][3] + b1));
            *(float2*)(outs[mat] + (size_t)(row0 + m0 + g    ) * HH + col) = v0;
            *(float2*)(outs[mat] + (size_t)(row0 + m0 + g + 8) * HH + col) = v1;
        }
    }
}

// ---------------------------------------------------------------------------
// Kernel 2: causal flash attention, tf32 mma + ldmatrix, split-KV, cp.async.
// ---------------------------------------------------------------------------
#define PITCH 68
#define TILE_F (64*PITCH)
#define QS_OFF 0
#define KS_OFF TILE_F
#define VS_OFF (KS_OFF + 4*TILE_F)
#define PS_OFF (VS_OFF + 4*TILE_F)
#define SM_FLOATS (PS_OFF + 8*16*PITCH)
#define SCL 0.18033688011112042f

__device__ __forceinline__ void attn_prefetch(
    float* sm, const float* kbase, const float* vbase,
    int tid, int tbase, int nt, int j)
{
    const int buf = j & 1;
#pragma unroll
    for (int t = 0; t < 16; t++) {
        int cidf = tid + t * 256;
        int sel  = cidf >> 10;
        int cid  = cidf & 1023;
        int row  = cid >> 4, c16 = cid & 15;
        int jt   = 2 * j + (sel & 1);
        if (jt < nt) {
            const float* src = ((sel >> 1) ? vbase : kbase)
                               + ((size_t)((tbase + jt) * 64 + row)) * HH + c16 * 4;
            float* dst = sm + ((sel >> 1) ? VS_OFF : KS_OFF)
                         + ((sel & 1) * 2 + buf) * TILE_F + row * PITCH + c16 * 4;
            cp16(dst, src);
        }
    }
}

__global__ __launch_bounds__(256) void attn_kernel(float* __restrict__ out)
{
    extern __shared__ float sm[];

    const int b   = blockIdx.y;
    const int tid = threadIdx.x;
    const int wid = tid >> 5, l = tid & 31, g = l >> 2, tg = l & 3;
    const int mt  = wid & 3;
    const int s   = wid >> 2;

    int qi = 0, ch = 0;
    {
        int wl = blockIdx.x, acc = 0;
        for (int ii = 31; ii >= 0; ii--) {
            int nc = (ii + 8) >> 3;
            if (wl < acc + nc) { qi = ii; ch = wl - acc; break; }
            acc += nc;
        }
    }
    const int qt0    = qi * 64;
    const int ntiles = qi + 1;
    const int nch    = (qi + 8) >> 3;
    const int tbase  = ch * 8;
    int nt = ntiles - tbase; if (nt > 8) nt = 8;
    const int ns = (nt + 1) >> 1;

    const float* kbase = g_k + (size_t)b * TT * HH;
    const float* vbase = g_v + (size_t)b * TT * HH;

    {
        const float* qsrc = g_q + ((size_t)b * TT + qt0) * HH;
#pragma unroll
        for (int t = 0; t < 4; t++) {
            int cid = tid + t * 256;
            int row = cid >> 4, c16 = cid & 15;
            cp16(sm + QS_OFF + row * PITCH + c16 * 4, qsrc + row * HH + c16 * 4);
        }
        attn_prefetch(sm, kbase, vbase, tid, tbase, nt, 0);
        CP_COMMIT();
    }

    const unsigned smu = (unsigned)__cvta_generic_to_shared(sm);
    // fragment offsets (bytes)
    const unsigned a16off = ((l & 15) * PITCH + ((l & 16) >> 2)) * 4;       // A-type (Q/P)
    const unsigned bkoff  = (((l & 7) + ((l & 16) >> 1)) * PITCH + ((l & 8) >> 1)) * 4; // B-type (K)
    const unsigned qs_u32 = smu + (QS_OFF + mt * 16 * PITCH) * 4 + a16off;
    const unsigned ps_u32 = smu + (PS_OFF + wid * 16 * PITCH) * 4 + a16off;

    unsigned qreg[8][4];
    float o[8][4];
    float m_lo = -INFINITY, m_hi = -INFINITY, l_lo = 0.f, l_hi = 0.f;
#pragma unroll
    for (int n = 0; n < 8; n++)
#pragma unroll
        for (int i = 0; i < 4; i++) o[n][i] = 0.0f;

    float* Ps = sm + PS_OFF + wid * (16 * PITCH);

    for (int j = 0; j < ns; j++) {
        const int buf = j & 1;
        if (j + 1 < ns) {
            attn_prefetch(sm, kbase, vbase, tid, tbase, nt, j + 1);
            CP_COMMIT();
            CP_WAIT1();
        } else {
            CP_WAIT0();
        }
        __syncthreads();

        if (j == 0) {
#pragma unroll
            for (int k8 = 0; k8 < 8; k8++)
                LDSM4(qreg[k8][0], qreg[k8][1], qreg[k8][2], qreg[k8][3],
                      qs_u32 + k8 * 32);
        }

        const int jt = 2 * j + s;
        if (jt < nt) {
            const int k0 = (tbase + jt) * 64;
            const unsigned kb_u32 = smu + (KS_OFF + (s * 2 + buf) * TILE_F) * 4 + bkoff;
            const float* Vb = sm + VS_OFF + (s * 2 + buf) * TILE_F;

            // ---- S = Q . K^T ----
            float sc[8][4];
#pragma unroll
            for (int n = 0; n < 8; n++)
#pragma unroll
                for (int i = 0; i < 4; i++) sc[n][i] = 0.0f;
#pragma unroll
            for (int k8 = 0; k8 < 8; k8++) {
#pragma unroll
                for (int n0p = 0; n0p < 4; n0p++) {
                    unsigned b0, b1, b2, b3;
                    LDSM4(b0, b1, b2, b3,
                          kb_u32 + n0p * (16 * PITCH * 4) + k8 * 32);
                    mma_tf32(sc[n0p*2    ], qreg[k8][0], qreg[k8][1], qreg[k8][2], qreg[k8][3], b0, b1);
                    mma_tf32(sc[n0p*2 + 1], qreg[k8][0], qreg[k8][1], qreg[k8][2], qreg[k8][3], b2, b3);
                }
            }

            // ---- masked online softmax (log2 domain) ----
            const int t_lo = qt0 + mt*16 + g;
            const int t_hi = t_lo + 8;
            float mx_lo = -INFINITY, mx_hi = -INFINITY;
            float u[8][4];
#pragma unroll
            for (int n0 = 0; n0 < 8; n0++) {
                int c0 = k0 + n0*8 + 2*tg, c1 = c0 + 1;
                u[n0][0] = (c0 <= t_lo) ? sc[n0][0] * SCL : -INFINITY;
                u[n0][1] = (c1 <= t_lo) ? sc[n0][1] * SCL : -INFINITY;
                u[n0][2] = (c0 <= t_hi) ? sc[n0][2] * SCL : -INFINITY;
                u[n0][3] = (c1 <= t_hi) ? sc[n0][3] * SCL : -INFINITY;
                mx_lo = fmaxf(mx_lo, fmaxf(u[n0][0], u[n0][1]));
                mx_hi = fmaxf(mx_hi, fmaxf(u[n0][2], u[n0][3]));
            }
            mx_lo = fmaxf(mx_lo, __shfl_xor_sync(0xffffffffu, mx_lo, 1));
            mx_lo = fmaxf(mx_lo, __shfl_xor_sync(0xffffffffu, mx_lo, 2));
            mx_hi = fmaxf(mx_hi, __shfl_xor_sync(0xffffffffu, mx_hi, 1));
            mx_hi = fmaxf(mx_hi, __shfl_xor_sync(0xffffffffu, mx_hi, 2));
            float mn_lo = fmaxf(m_lo, mx_lo);
            float mn_hi = fmaxf(m_hi, mx_hi);
            float f_lo = ex2(m_lo - mn_lo);
            float f_hi = ex2(m_hi - mn_hi);

            float sum_lo = 0.f, sum_hi = 0.f;
#pragma unroll
            for (int n0 = 0; n0 < 8; n0++) {
                float p0 = ex2(u[n0][0] - mn_lo);
                float p1 = ex2(u[n0][1] - mn_lo);
                float p2 = ex2(u[n0][2] - mn_hi);
                float p3 = ex2(u[n0][3] - mn_hi);
                sum_lo += p0 + p1;
                sum_hi += p2 + p3;
                float2 w0, w1;
                w0.x = __uint_as_float(f2tf32(p0)); w0.y = __uint_as_float(f2tf32(p1));
                w1.x = __uint_as_float(f2tf32(p2)); w1.y = __uint_as_float(f2tf32(p3));
                *(float2*)(Ps + (g    ) * PITCH + n0*8 + 2*tg) = w0;
                *(float2*)(Ps + (g + 8) * PITCH + n0*8 + 2*tg) = w1;
            }
            sum_lo += __shfl_xor_sync(0xffffffffu, sum_lo, 1);
            sum_lo += __shfl_xor_sync(0xffffffffu, sum_lo, 2);
            sum_hi += __shfl_xor_sync(0xffffffffu, sum_hi, 1);
            sum_hi += __shfl_xor_sync(0xffffffffu, sum_hi, 2);
            l_lo = l_lo * f_lo + sum_lo;
            l_hi = l_hi * f_hi + sum_hi;
            m_lo = mn_lo; m_hi = mn_hi;
#pragma unroll
            for (int n0 = 0; n0 < 8; n0++) {
                o[n0][0] *= f_lo; o[n0][1] *= f_lo;
                o[n0][2] *= f_hi; o[n0][3] *= f_hi;
            }
            __syncwarp();

            // ---- O += P . V ----
#pragma unroll
            for (int k8 = 0; k8 < 8; k8++) {
                unsigned a0, a1, a2, a3;
                LDSM4(a0, a1, a2, a3, ps_u32 + k8 * 32);
#pragma unroll
                for (int n0 = 0; n0 < 8; n0++) {
                    unsigned b0 = __float_as_uint(Vb[(k8*8 + tg    ) * PITCH + n0*8 + g]);
                    unsigned b1 = __float_as_uint(Vb[(k8*8 + tg + 4) * PITCH + n0*8 + g]);
                    mma_tf32(o[n0], a0, a1, a2, a3, b0, b1);
                }
            }
        }
        __syncthreads();
    }

    // ---- merge the two streams; write out or partials ----
    float* Om = sm + PS_OFF + mt * (16 * PITCH);
    float* Ml = sm + PS_OFF + 4 * (16 * PITCH) + mt * 32;
    if (s == 1) {
#pragma unroll
        for (int n0 = 0; n0 < 8; n0++) {
            *(float2*)(Om + (g    ) * PITCH + n0*8 + 2*tg) = make_float2(o[n0][0], o[n0][1]);
            *(float2*)(Om + (g + 8) * PITCH + n0*8 + 2*tg) = make_float2(o[n0][2], o[n0][3]);
        }
        Ml[g] = m_lo; Ml[g + 8] = m_hi;
        Ml[16 + g] = l_lo; Ml[16 + 8 + g] = l_hi;
    }
    __syncthreads();
    if (s == 0) {
        float m2_lo = Ml[g], m2_hi = Ml[g + 8];
        float l2_lo = Ml[16 + g], l2_hi = Ml[16 + 8 + g];
        float mf_lo = fmaxf(m_lo, m2_lo), mf_hi = fmaxf(m_hi, m2_hi);
        float a_lo = ex2(m_lo - mf_lo), b_lo = ex2(m2_lo - mf_lo);
        float a_hi = ex2(m_hi - mf_hi), b_hi = ex2(m2_hi - mf_hi);
        float lm_lo = l_lo * a_lo + l2_lo * b_lo;
        float lm_hi = l_hi * a_hi + l2_hi * b_hi;
        const int r_lo = mt*16 + g, r_hi = r_lo + 8;

        if (nch == 1) {
            float inv_lo = 1.0f / lm_lo, inv_hi = 1.0f / lm_hi;
#pragma unroll
            for (int n0 = 0; n0 < 8; n0++) {
                float2 o2l = *(float2*)(Om + (g    ) * PITCH + n0*8 + 2*tg);
                float2 o2h = *(float2*)(Om + (g + 8) * PITCH + n0*8 + 2*tg);
                float2 r0, r1;
                r0.x = (o[n0][0] * a_lo + o2l.x * b_lo) * inv_lo;
                r0.y = (o[n0][1] * a_lo + o2l.y * b_lo) * inv_lo;
                r1.x = (o[n0][2] * a_hi + o2h.x * b_hi) * inv_hi;
                r1.y = (o[n0][3] * a_hi + o2h.y * b_hi) * inv_hi;
                *(float2*)(out + ((size_t)b * TT + qt0 + r_lo) * HH + n0*8 + 2*tg) = r0;
                *(float2*)(out + ((size_t)b * TT + qt0 + r_hi) * HH + n0*8 + 2*tg) = r1;
            }
        } else {
            const int pidx = (b * 32 + qi) * 4 + ch;
            float* pod = g_po + (size_t)pidx * 4096;
#pragma unroll
            for (int n0 = 0; n0 < 8; n0++) {
                float2 o2l = *(float2*)(Om + (g    ) * PITCH + n0*8 + 2*tg);
                float2 o2h = *(float2*)(Om + (g + 8) * PITCH + n0*8 + 2*tg);
                float2 r0, r1;
                r0.x = o[n0][0] * a_lo + o2l.x * b_lo;
                r0.y = o[n0][1] * a_lo + o2l.y * b_lo;
                r1.x = o[n0][2] * a_hi + o2h.x * b_hi;
                r1.y = o[n0][3] * a_hi + o2h.y * b_hi;
                *(float2*)(pod + r_lo * 64 + n0*8 + 2*tg) = r0;
                *(float2*)(pod + r_hi * 64 + n0*8 + 2*tg) = r1;
            }
            if (tg == 0) {
                g_ml[pidx*128 + r_lo*2] = mf_lo; g_ml[pidx*128 + r_lo*2 + 1] = lm_lo;
                g_ml[pidx*128 + r_hi*2] = mf_hi; g_ml[pidx*128 + r_hi*2 + 1] = lm_hi;
            }
        }
    }
}

// ---------------------------------------------------------------------------
// Kernel 3: merge split-KV partials (qi >= 8).  grid (24, 4), block 256.
// ---------------------------------------------------------------------------
__global__ __launch_bounds__(256) void merge_kernel(float* __restrict__ out)
{
    const int qi  = 8 + blockIdx.x;
    const int b   = blockIdx.y;
    const int nch = (qi + 8) >> 3;
    const int tid = threadIdx.x;
    const int r   = tid >> 2;
    const int cg  = (tid & 3) * 16;
    const int pbase = (b * 32 + qi) * 4;

    float mv[4], lv[4], e[4];
    float mf = -INFINITY;
    for (int c = 0; c < nch; c++) {
        mv[c] = g_ml[(pbase + c)*128 + r*2];
        lv[c] = g_ml[(pbase + c)*128 + r*2 + 1];
        mf = fmaxf(mf, mv[c]);
    }
    float wsum = 0.f;
    for (int c = 0; c < nch; c++) { e[c] = ex2(mv[c] - mf); wsum += lv[c] * e[c]; }
    float inv = 1.0f / wsum;

    size_t obase = ((size_t)b * TT + qi * 64 + r) * HH;
#pragma unroll
    for (int c4 = 0; c4 < 4; c4++) {
        float4 a = make_float4(0.f, 0.f, 0.f, 0.f);
        for (int c = 0; c < nch; c++) {
            const float4 p = *(const float4*)(g_po + (size_t)(pbase + c)*4096 + r*64 + cg + c4*4);
            a.x += e[c]*p.x; a.y += e[c]*p.y; a.z += e[c]*p.z; a.w += e[c]*p.w;
        }
        a.x *= inv; a.y *= inv; a.z *= inv; a.w *= inv;
        *(float4*)(out + obase + cg + c4*4) = a;
    }
}

// ---------------------------------------------------------------------------
extern "C" void kernel_launch(void* const* d_in, const int* in_sizes, int n_in,
                              void* d_out, int out_size)
{
    const float* x  = (const float*)d_in[0];
    const float* Wq = (const float*)d_in[1];
    const float* bq = (const float*)d_in[2];
    const float* Wk = (const float*)d_in[3];
    const float* bk = (const float*)d_in[4];
    const float* Wv = (const float*)d_in[5];
    const float* bv = (const float*)d_in[6];
    float* out = (float*)d_out;

    proj_kernel<<<MM / 64, 256>>>(x, Wq, bq, Wk, bk, Wv, bv);

    const int smem_bytes = SM_FLOATS * sizeof(float);
    cudaFuncSetAttribute(attn_kernel, cudaFuncAttributeMaxDynamicSharedMemorySize, smem_bytes);
    attn_kernel<<<dim3(80, BB), 256, smem_bytes>>>(out);

    merge_kernel<<<dim3(24, BB), 256>>>(out);
}

// round 7
// speedup vs baseline: 3.7261x; 1.0291x over previous
#include <cuda_runtime.h>
#include <math.h>

#define BB 4
#define TT 2048
#define EE 1024
#define HH 64
#define MM (BB*TT)

// device scratch (module statics: allocation-free)
__device__ float g_q[MM*HH];
__device__ float g_k[MM*HH];
__device__ float g_v[MM*HH];
// split-KV partials: pidx = (b*32 + qtile)*4 + chunk
__device__ float g_po[512*64*64];
__device__ float g_ml[512*64*2];

__device__ __forceinline__ unsigned f2tf32(float f) {
    unsigned u;
    asm("cvt.rna.tf32.f32 %0, %1;" : "=r"(u) : "f"(f));
    return u;
}
__device__ __forceinline__ unsigned u2tf32(unsigned ub) {
    unsigned u;
    asm("cvt.rna.tf32.f32 %0, %1;" : "=r"(u) : "f"(__uint_as_float(ub)));
    return u;
}
__device__ __forceinline__ float ex2(float x) {
    float y;
    asm("ex2.approx.ftz.f32 %0, %1;" : "=f"(y) : "f"(x));
    return y;
}
__device__ __forceinline__ void mma_tf32(float c[4], unsigned a0, unsigned a1,
                                         unsigned a2, unsigned a3,
                                         unsigned b0, unsigned b1) {
    asm volatile(
        "mma.sync.aligned.m16n8k8.row.col.f32.tf32.tf32.f32 "
        "{%0,%1,%2,%3}, {%4,%5,%6,%7}, {%8,%9}, {%0,%1,%2,%3};"
        : "+f"(c[0]), "+f"(c[1]), "+f"(c[2]), "+f"(c[3])
        : "r"(a0), "r"(a1), "r"(a2), "r"(a3), "r"(b0), "r"(b1));
}
// ldmatrix x4 on 32-bit data: each float row segment = 2 b16 columns.
#define LDSM4(r0,r1,r2,r3,addr) \
    asm volatile("ldmatrix.sync.aligned.m8n8.x4.shared.b16 {%0,%1,%2,%3}, [%4];" \
                 : "=r"(r0), "=r"(r1), "=r"(r2), "=r"(r3) : "r"(addr))

__device__ __forceinline__ void cp16(void* smem, const void* gmem) {
    unsigned sa = (unsigned)__cvta_generic_to_shared(smem);
    asm volatile("cp.async.cg.shared.global [%0], [%1], 16;" :: "r"(sa), "l"(gmem));
}
#define CP_COMMIT() asm volatile("cp.async.commit_group;")
#define CP_WAIT0()  asm volatile("cp.async.wait_group 0;")
#define CP_WAIT1()  asm volatile("cp.async.wait_group 1;")
#define CP_WAIT2()  asm volatile("cp.async.wait_group 2;")

// ---------------------------------------------------------------------------
// Kernel 1: FUSED QKV projection, tf32 mma + ldmatrix + 4-stage cp.async ring.
// grid 128 (64 rows/block), block 256 (8 warps: 4 m-tiles x 2 n-halves).
// smem raw fp32; cvt.rna applied to fragment registers after LDSM.
// Per chunk: wait_group -> sync -> LDSM/cvt/MMA -> prefetch(kc+3)+commit.
// Stage: X[64][20] + 3x W[64][20] fp32 = 20480 B; 4 stages = 80 KB.
// ---------------------------------------------------------------------------
__global__ __launch_bounds__(256) void proj_kernel(
    const float* __restrict__ x,
    const float* __restrict__ Wq, const float* __restrict__ bq,
    const float* __restrict__ Wk, const float* __restrict__ bk,
    const float* __restrict__ Wv, const float* __restrict__ bv)
{
    __shared__ __align__(16) float smp[4][4*1280];   // 80 KB

    const int row0 = blockIdx.x * 64;
    const int tid = threadIdx.x;
    const int wid = tid >> 5, l = tid & 31, tg = l & 3;
    const int m0 = (wid & 3) * 16;
    const int nb = (wid >> 2) * 32;

    // loader mapping: thread -> row 0..63, float4 column
    const int lrow = tid >> 2;
    const int lc4  = (tid & 3) * 4;

    const float* srcs[4];
    srcs[0] = x  + (size_t)(row0 + lrow) * EE + lc4;
    srcs[1] = Wq + (size_t)lrow * EE + lc4;
    srcs[2] = Wk + (size_t)lrow * EE + lc4;
    srcs[3] = Wv + (size_t)lrow * EE + lc4;

#define PREF(kc) { _Pragma("unroll") for (int a = 0; a < 4; a++) \
                       cp16(&smp[(kc)&3][a*1280 + lrow*20 + lc4], srcs[a] + (kc)*16); \
                   CP_COMMIT(); }

    float acc[3][4][4];
#pragma unroll
    for (int mat = 0; mat < 3; mat++)
#pragma unroll
        for (int n = 0; n < 4; n++)
#pragma unroll
            for (int i = 0; i < 4; i++) acc[mat][n][i] = 0.0f;

    const unsigned sb = (unsigned)__cvta_generic_to_shared(&smp[0][0]);
    // fragment offsets within a stage (bytes)
    const unsigned aoff = ((m0 + (l & 15)) * 20 + ((l & 16) >> 2)) * 4;
    const unsigned boff = ((nb + (l & 7) + ((l & 16) >> 1)) * 20 + ((l & 8) >> 1)) * 4;

    PREF(0); PREF(1); PREF(2);

    for (int kc = 0; kc < 64; kc++) {
        if (kc < 62)      { CP_WAIT2(); }
        else if (kc == 62){ CP_WAIT1(); }
        else              { CP_WAIT0(); }
        __syncthreads();

        const unsigned stg = sb + (kc & 3) * 20480;
#pragma unroll
        for (int k8 = 0; k8 < 16; k8 += 8) {
            unsigned a0, a1, a2, a3;
            LDSM4(a0, a1, a2, a3, stg + aoff + k8 * 4);
            a0 = u2tf32(a0); a1 = u2tf32(a1); a2 = u2tf32(a2); a3 = u2tf32(a3);
#pragma unroll
            for (int mat = 0; mat < 3; mat++) {
#pragma unroll
                for (int n0p = 0; n0p < 2; n0p++) {
                    unsigned b0, b1, b2, b3;
                    LDSM4(b0, b1, b2, b3,
                          stg + 5120 + mat * 5120 + boff + n0p * 1280 + k8 * 4);
                    b0 = u2tf32(b0); b1 = u2tf32(b1);
                    b2 = u2tf32(b2); b3 = u2tf32(b3);
                    mma_tf32(acc[mat][n0p*2    ], a0, a1, a2, a3, b0, b1);
                    mma_tf32(acc[mat][n0p*2 + 1], a0, a1, a2, a3, b2, b3);
                }
            }
        }
        if (kc + 3 < 64) PREF(kc + 3);
    }

    const int g = l >> 2;
    const float* bs[3] = {bq, bk, bv};
    float* outs[3] = {g_q, g_k, g_v};
#pragma unroll
    for (int mat = 0; mat < 3; mat++) {
#pragma unroll
        for (int n0 = 0; n0 < 4; n0++) {
            int col = nb + n0 * 8 + 2 * tg;
            float b0 = bs[mat][col], b1 = bs[mat][col + 1];
            float2 v0, v1;
            v0.x = __uint_as_float(f2tf32(acc[mat][n0][0] + b0));
            v0.y = __uint_as_float(f2tf32(acc[mat][n0][1] + b1));
            v1.x = __uint_as_float(f2tf32(acc[mat][n0][2] + b0));
            v1.y = __uint_as_float(f2tf32(acc[mat][n0][3] + b1));
            *(float2*)(outs[mat] + (size_t)(row0 + m0 + g    ) * HH + col) = v0;
            *(float2*)(outs[mat] + (size_t)(row0 + m0 + g + 8) * HH + col) = v1;
        }
    }
}

// ---------------------------------------------------------------------------
// Kernel 2: causal flash attention, tf32 mma + ldmatrix, split-KV, cp.async.
// (unchanged from R6)
// ---------------------------------------------------------------------------
#define PITCH 68
#define TILE_F (64*PITCH)
#define QS_OFF 0
#define KS_OFF TILE_F
#define VS_OFF (KS_OFF + 4*TILE_F)
#define PS_OFF (VS_OFF + 4*TILE_F)
#define SM_FLOATS (PS_OFF + 8*16*PITCH)
#define SCL 0.18033688011112042f

__device__ __forceinline__ void attn_prefetch(
    float* sm, const float* kbase, const float* vbase,
    int tid, int tbase, int nt, int j)
{
    const int buf = j & 1;
#pragma unroll
    for (int t = 0; t < 16; t++) {
        int cidf = tid + t * 256;
        int sel  = cidf >> 10;
        int cid  = cidf & 1023;
        int row  = cid >> 4, c16 = cid & 15;
        int jt   = 2 * j + (sel & 1);
        if (jt < nt) {
            const float* src = ((sel >> 1) ? vbase : kbase)
                               + ((size_t)((tbase + jt) * 64 + row)) * HH + c16 * 4;
            float* dst = sm + ((sel >> 1) ? VS_OFF : KS_OFF)
                         + ((sel & 1) * 2 + buf) * TILE_F + row * PITCH + c16 * 4;
            cp16(dst, src);
        }
    }
}

__global__ __launch_bounds__(256) void attn_kernel(float* __restrict__ out)
{
    extern __shared__ float sm[];

    const int b   = blockIdx.y;
    const int tid = threadIdx.x;
    const int wid = tid >> 5, l = tid & 31, g = l >> 2, tg = l & 3;
    const int mt  = wid & 3;
    const int s   = wid >> 2;

    int qi = 0, ch = 0;
    {
        int wl = blockIdx.x, acc = 0;
        for (int ii = 31; ii >= 0; ii--) {
            int nc = (ii + 8) >> 3;
            if (wl < acc + nc) { qi = ii; ch = wl - acc; break; }
            acc += nc;
        }
    }
    const int qt0    = qi * 64;
    const int ntiles = qi + 1;
    const int nch    = (qi + 8) >> 3;
    const int tbase  = ch * 8;
    int nt = ntiles - tbase; if (nt > 8) nt = 8;
    const int ns = (nt + 1) >> 1;

    const float* kbase = g_k + (size_t)b * TT * HH;
    const float* vbase = g_v + (size_t)b * TT * HH;

    {
        const float* qsrc = g_q + ((size_t)b * TT + qt0) * HH;
#pragma unroll
        for (int t = 0; t < 4; t++) {
            int cid = tid + t * 256;
            int row = cid >> 4, c16 = cid & 15;
            cp16(sm + QS_OFF + row * PITCH + c16 * 4, qsrc + row * HH + c16 * 4);
        }
        attn_prefetch(sm, kbase, vbase, tid, tbase, nt, 0);
        CP_COMMIT();
    }

    const unsigned smu = (unsigned)__cvta_generic_to_shared(sm);
    const unsigned a16off = ((l & 15) * PITCH + ((l & 16) >> 2)) * 4;
    const unsigned bkoff  = (((l & 7) + ((l & 16) >> 1)) * PITCH + ((l & 8) >> 1)) * 4;
    const unsigned qs_u32 = smu + (QS_OFF + mt * 16 * PITCH) * 4 + a16off;
    const unsigned ps_u32 = smu + (PS_OFF + wid * 16 * PITCH) * 4 + a16off;

    unsigned qreg[8][4];
    float o[8][4];
    float m_lo = -INFINITY, m_hi = -INFINITY, l_lo = 0.f, l_hi = 0.f;
#pragma unroll
    for (int n = 0; n < 8; n++)
#pragma unroll
        for (int i = 0; i < 4; i++) o[n][i] = 0.0f;

    float* Ps = sm + PS_OFF + wid * (16 * PITCH);

    for (int j = 0; j < ns; j++) {
        const int buf = j & 1;
        if (j + 1 < ns) {
            attn_prefetch(sm, kbase, vbase, tid, tbase, nt, j + 1);
            CP_COMMIT();
            CP_WAIT1();
        } else {
            CP_WAIT0();
        }
        __syncthreads();

        if (j == 0) {
#pragma unroll
            for (int k8 = 0; k8 < 8; k8++)
                LDSM4(qreg[k8][0], qreg[k8][1], qreg[k8][2], qreg[k8][3],
                      qs_u32 + k8 * 32);
        }

        const int jt = 2 * j + s;
        if (jt < nt) {
            const int k0 = (tbase + jt) * 64;
            const unsigned kb_u32 = smu + (KS_OFF + (s * 2 + buf) * TILE_F) * 4 + bkoff;
            const float* Vb = sm + VS_OFF + (s * 2 + buf) * TILE_F;

            float sc[8][4];
#pragma unroll
            for (int n = 0; n < 8; n++)
#pragma unroll
                for (int i = 0; i < 4; i++) sc[n][i] = 0.0f;
#pragma unroll
            for (int k8 = 0; k8 < 8; k8++) {
#pragma unroll
                for (int n0p = 0; n0p < 4; n0p++) {
                    unsigned b0, b1, b2, b3;
                    LDSM4(b0, b1, b2, b3,
                          kb_u32 + n0p * (16 * PITCH * 4) + k8 * 32);
                    mma_tf32(sc[n0p*2    ], qreg[k8][0], qreg[k8][1], qreg[k8][2], qreg[k8][3], b0, b1);
                    mma_tf32(sc[n0p*2 + 1], qreg[k8][0], qreg[k8][1], qreg[k8][2], qreg[k8][3], b2, b3);
                }
            }

            const int t_lo = qt0 + mt*16 + g;
            const int t_hi = t_lo + 8;
            float mx_lo = -INFINITY, mx_hi = -INFINITY;
            float u[8][4];
#pragma unroll
            for (int n0 = 0; n0 < 8; n0++) {
                int c0 = k0 + n0*8 + 2*tg, c1 = c0 + 1;
                u[n0][0] = (c0 <= t_lo) ? sc[n0][0] * SCL : -INFINITY;
                u[n0][1] = (c1 <= t_lo) ? sc[n0][1] * SCL : -INFINITY;
                u[n0][2] = (c0 <= t_hi) ? sc[n0][2] * SCL : -INFINITY;
                u[n0][3] = (c1 <= t_hi) ? sc[n0][3] * SCL : -INFINITY;
                mx_lo = fmaxf(mx_lo, fmaxf(u[n0][0], u[n0][1]));
                mx_hi = fmaxf(mx_hi, fmaxf(u[n0][2], u[n0][3]));
            }
            mx_lo = fmaxf(mx_lo, __shfl_xor_sync(0xffffffffu, mx_lo, 1));
            mx_lo = fmaxf(mx_lo, __shfl_xor_sync(0xffffffffu, mx_lo, 2));
            mx_hi = fmaxf(mx_hi, __shfl_xor_sync(0xffffffffu, mx_hi, 1));
            mx_hi = fmaxf(mx_hi, __shfl_xor_sync(0xffffffffu, mx_hi, 2));
            float mn_lo = fmaxf(m_lo, mx_lo);
            float mn_hi = fmaxf(m_hi, mx_hi);
            float f_lo = ex2(m_lo - mn_lo);
            float f_hi = ex2(m_hi - mn_hi);

            float sum_lo = 0.f, sum_hi = 0.f;
#pragma unroll
            for (int n0 = 0; n0 < 8; n0++) {
                float p0 = ex2(u[n0][0] - mn_lo);
                float p1 = ex2(u[n0][1] - mn_lo);
                float p2 = ex2(u[n0][2] - mn_hi);
                float p3 = ex2(u[n0][3] - mn_hi);
                sum_lo += p0 + p1;
                sum_hi += p2 + p3;
                float2 w0, w1;
                w0.x = __uint_as_float(f2tf32(p0)); w0.y = __uint_as_float(f2tf32(p1));
                w1.x = __uint_as_float(f2tf32(p2)); w1.y = __uint_as_float(f2tf32(p3));
                *(float2*)(Ps + (g    ) * PITCH + n0*8 + 2*tg) = w0;
                *(float2*)(Ps + (g + 8) * PITCH + n0*8 + 2*tg) = w1;
            }
            sum_lo += __shfl_xor_sync(0xffffffffu, sum_lo, 1);
            sum_lo += __shfl_xor_sync(0xffffffffu, sum_lo, 2);
            sum_hi += __shfl_xor_sync(0xffffffffu, sum_hi, 1);
            sum_hi += __shfl_xor_sync(0xffffffffu, sum_hi, 2);
            l_lo = l_lo * f_lo + sum_lo;
            l_hi = l_hi * f_hi + sum_hi;
            m_lo = mn_lo; m_hi = mn_hi;
#pragma unroll
            for (int n0 = 0; n0 < 8; n0++) {
                o[n0][0] *= f_lo; o[n0][1] *= f_lo;
                o[n0][2] *= f_hi; o[n0][3] *= f_hi;
            }
            __syncwarp();

#pragma unroll
            for (int k8 = 0; k8 < 8; k8++) {
                unsigned a0, a1, a2, a3;
                LDSM4(a0, a1, a2, a3, ps_u32 + k8 * 32);
#pragma unroll
                for (int n0 = 0; n0 < 8; n0++) {
                    unsigned b0 = __float_as_uint(Vb[(k8*8 + tg    ) * PITCH + n0*8 + g]);
                    unsigned b1 = __float_as_uint(Vb[(k8*8 + tg + 4) * PITCH + n0*8 + g]);
                    mma_tf32(o[n0], a0, a1, a2, a3, b0, b1);
                }
            }
        }
        __syncthreads();
    }

    float* Om = sm + PS_OFF + mt * (16 * PITCH);
    float* Ml = sm + PS_OFF + 4 * (16 * PITCH) + mt * 32;
    if (s == 1) {
#pragma unroll
        for (int n0 = 0; n0 < 8; n0++) {
            *(float2*)(Om + (g    ) * PITCH + n0*8 + 2*tg) = make_float2(o[n0][0], o[n0][1]);
            *(float2*)(Om + (g + 8) * PITCH + n0*8 + 2*tg) = make_float2(o[n0][2], o[n0][3]);
        }
        Ml[g] = m_lo; Ml[g + 8] = m_hi;
        Ml[16 + g] = l_lo; Ml[16 + 8 + g] = l_hi;
    }
    __syncthreads();
    if (s == 0) {
        float m2_lo = Ml[g], m2_hi = Ml[g + 8];
        float l2_lo = Ml[16 + g], l2_hi = Ml[16 + 8 + g];
        float mf_lo = fmaxf(m_lo, m2_lo), mf_hi = fmaxf(m_hi, m2_hi);
        float a_lo = ex2(m_lo - mf_lo), b_lo = ex2(m2_lo - mf_lo);
        float a_hi = ex2(m_hi - mf_hi), b_hi = ex2(m2_hi - mf_hi);
        float lm_lo = l_lo * a_lo + l2_lo * b_lo;
        float lm_hi = l_hi * a_hi + l2_hi * b_hi;
        const int r_lo = mt*16 + g, r_hi = r_lo + 8;

        if (nch == 1) {
            float inv_lo = 1.0f / lm_lo, inv_hi = 1.0f / lm_hi;
#pragma unroll
            for (int n0 = 0; n0 < 8; n0++) {
                float2 o2l = *(float2*)(Om + (g    ) * PITCH + n0*8 + 2*tg);
                float2 o2h = *(float2*)(Om + (g + 8) * PITCH + n0*8 + 2*tg);
                float2 r0, r1;
                r0.x = (o[n0][0] * a_lo + o2l.x * b_lo) * inv_lo;
                r0.y = (o[n0][1] * a_lo + o2l.y * b_lo) * inv_lo;
                r1.x = (o[n0][2] * a_hi + o2h.x * b_hi) * inv_hi;
                r1.y = (o[n0][3] * a_hi + o2h.y * b_hi) * inv_hi;
                *(float2*)(out + ((size_t)b * TT + qt0 + r_lo) * HH + n0*8 + 2*tg) = r0;
                *(float2*)(out + ((size_t)b * TT + qt0 + r_hi) * HH + n0*8 + 2*tg) = r1;
            }
        } else {
            const int pidx = (b * 32 + qi) * 4 + ch;
            float* pod = g_po + (size_t)pidx * 4096;
#pragma unroll
            for (int n0 = 0; n0 < 8; n0++) {
                float2 o2l = *(float2*)(Om + (g    ) * PITCH + n0*8 + 2*tg);
                float2 o2h = *(float2*)(Om + (g + 8) * PITCH + n0*8 + 2*tg);
                float2 r0, r1;
                r0.x = o[n0][0] * a_lo + o2l.x * b_lo;
                r0.y = o[n0][1] * a_lo + o2l.y * b_lo;
                r1.x = o[n0][2] * a_hi + o2h.x * b_hi;
                r1.y = o[n0][3] * a_hi + o2h.y * b_hi;
                *(float2*)(pod + r_lo * 64 + n0*8 + 2*tg) = r0;
                *(float2*)(pod + r_hi * 64 + n0*8 + 2*tg) = r1;
            }
            if (tg == 0) {
                g_ml[pidx*128 + r_lo*2] = mf_lo; g_ml[pidx*128 + r_lo*2 + 1] = lm_lo;
                g_ml[pidx*128 + r_hi*2] = mf_hi; g_ml[pidx*128 + r_hi*2 + 1] = lm_hi;
            }
        }
    }
}

// ---------------------------------------------------------------------------
// Kernel 3: merge split-KV partials (qi >= 8).  grid (24, 4), block 256.
// ---------------------------------------------------------------------------
__global__ __launch_bounds__(256) void merge_kernel(float* __restrict__ out)
{
    const int qi  = 8 + blockIdx.x;
    const int b   = blockIdx.y;
    const int nch = (qi + 8) >> 3;
    const int tid = threadIdx.x;
    const int r   = tid >> 2;
    const int cg  = (tid & 3) * 16;
    const int pbase = (b * 32 + qi) * 4;

    float mv[4], lv[4], e[4];
    float mf = -INFINITY;
    for (int c = 0; c < nch; c++) {
        mv[c] = g_ml[(pbase + c)*128 + r*2];
        lv[c] = g_ml[(pbase + c)*128 + r*2 + 1];
        mf = fmaxf(mf, mv[c]);
    }
    float wsum = 0.f;
    for (int c = 0; c < nch; c++) { e[c] = ex2(mv[c] - mf); wsum += lv[c] * e[c]; }
    float inv = 1.0f / wsum;

    size_t obase = ((size_t)b * TT + qi * 64 + r) * HH;
#pragma unroll
    for (int c4 = 0; c4 < 4; c4++) {
        float4 a = make_float4(0.f, 0.f, 0.f, 0.f);
        for (int c = 0; c < nch; c++) {
            const float4 p = *(const float4*)(g_po + (size_t)(pbase + c)*4096 + r*64 + cg + c4*4);
            a.x += e[c]*p.x; a.y += e[c]*p.y; a.z += e[c]*p.z; a.w += e[c]*p.w;
        }
        a.x *= inv; a.y *= inv; a.z *= inv; a.w *= inv;
        *(float4*)(out + obase + cg + c4*4) = a;
    }
}

// ---------------------------------------------------------------------------
extern "C" void kernel_launch(void* const* d_in, const int* in_sizes, int n_in,
                              void* d_out, int out_size)
{
    const float* x  = (const float*)d_in[0];
    const float* Wq = (const float*)d_in[1];
    const float* bq = (const float*)d_in[2];
    const float* Wk = (const float*)d_in[3];
    const float* bk = (const float*)d_in[4];
    const float* Wv = (const float*)d_in[5];
    const float* bv = (const float*)d_in[6];
    float* out = (float*)d_out;

    proj_kernel<<<MM / 64, 256>>>(x, Wq, bq, Wk, bk, Wv, bv);

    const int smem_bytes = SM_FLOATS * sizeof(float);
    cudaFuncSetAttribute(attn_kernel, cudaFuncAttributeMaxDynamicSharedMemorySize, smem_bytes);
    attn_kernel<<<dim3(80, BB), 256, smem_bytes>>>(out);

    merge_kernel<<<dim3(24, BB), 256>>>(out);
}